// round 11
// baseline (speedup 1.0000x reference)
#include <cuda_runtime.h>
#include <cstdint>
#include <math.h>

// ---------------- problem constants ----------------
#define NXV 16384
#define BV  16
#define TP  64            // points per block
#define NT  256           // threads per block (8 warps)
#define NBLK (BV * (NXV / TP))   // 4096

// ---------------- swizzled A-tile addressing ----------------
__device__ __forceinline__ int SW(int row, int k) {
    return row * 128 + (k ^ ((row & 7) << 2));
}

// ---------------- smem layout (float offsets) ----------------
#define S_A   0                  // activation / C / G2 buffer 64 x 128 (32KB)
#define S_U   8192               // u halo (70 -> 72)
#define S_X   (S_U + 72)
#define SMEM_FLOATS (S_X + 72)   // 8336 floats = 33344 B  -> 3 CTAs/SM

#define WIMG_FLOATS 40960        // weight fragment images live in GLOBAL (L1/L2-resident)
__device__ float W_IMG[WIMG_FLOATS];

typedef unsigned long long u64;

// ---------------- packed helpers ----------------
__device__ __forceinline__ u64 pk2(float lo, float hi) {
    u64 r; asm("mov.b64 %0,{%1,%2};" : "=l"(r) : "f"(lo), "f"(hi)); return r;
}

// ---------------- gelu: A&S 7.1.28, one asm block (identical math to R9) ----------------
struct GConst { u64 CINV, ABSM, A6, A5, A4, A3, A2, A1, ONE, NCV, HALF; };
__device__ __forceinline__ GConst make_gc() {
    GConst g;
    g.CINV = 0x3F3504F33F3504F3ULL;
    g.ABSM = 0x7FFFFFFF7FFFFFFFULL;
    g.A6   = pk2(0.0000430638f, 0.0000430638f);
    g.A5   = pk2(0.0002765672f, 0.0002765672f);
    g.A4   = pk2(0.0001520143f, 0.0001520143f);
    g.A3   = pk2(0.0092705272f, 0.0092705272f);
    g.A2   = pk2(0.0422820123f, 0.0422820123f);
    g.A1   = pk2(0.0705230784f, 0.0705230784f);
    g.ONE  = 0x3F8000003F800000ULL;
    g.NCV  = 0xBF3504F3BF3504F3ULL;
    g.HALF = 0x3F0000003F000000ULL;
    return g;
}

__device__ __forceinline__ void gelu2_acc2(float tlo, float thi,
                                           float& slo, float& shi, const GConst& g) {
    asm("{\n\t"
        ".reg .b64 t2,s2,ax,d,r;\n\t"
        ".reg .f32 dl,dh;\n\t"
        "mov.b64 t2,{%2,%3};\n\t"
        "mov.b64 s2,{%0,%1};\n\t"
        "mul.rn.f32x2 ax,t2,%4;\n\t"
        "and.b64 ax,ax,%5;\n\t"
        "fma.rn.f32x2 d,ax,%6,%7;\n\t"
        "fma.rn.f32x2 d,d,ax,%8;\n\t"
        "fma.rn.f32x2 d,d,ax,%9;\n\t"
        "fma.rn.f32x2 d,d,ax,%10;\n\t"
        "fma.rn.f32x2 d,d,ax,%11;\n\t"
        "fma.rn.f32x2 d,d,ax,%12;\n\t"
        "mov.b64 {dl,dh},d;\n\t"
        "rcp.approx.f32 dl,dl;\n\t"
        "rcp.approx.f32 dh,dh;\n\t"
        "mov.b64 r,{dl,dh};\n\t"
        "mul.rn.f32x2 r,r,r;\n\t"
        "mul.rn.f32x2 r,r,r;\n\t"
        "mul.rn.f32x2 r,r,r;\n\t"
        "mul.rn.f32x2 r,r,r;\n\t"
        "fma.rn.f32x2 r,r,%13,%4;\n\t"
        "fma.rn.f32x2 s2,t2,%14,s2;\n\t"
        "fma.rn.f32x2 s2,ax,r,s2;\n\t"
        "mov.b64 {%0,%1},s2;\n\t"
        "}"
        : "+f"(slo), "+f"(shi)
        : "f"(tlo), "f"(thi),
          "l"(g.CINV), "l"(g.ABSM), "l"(g.A6), "l"(g.A5), "l"(g.A4),
          "l"(g.A3), "l"(g.A2), "l"(g.A1), "l"(g.ONE), "l"(g.NCV), "l"(g.HALF));
}

__device__ __forceinline__ void gelu2p(float tlo, float thi,
                                       float& olo, float& ohi, const GConst& g) {
    asm("{\n\t"
        ".reg .b64 t2,ax,d,r;\n\t"
        ".reg .f32 dl,dh;\n\t"
        "mov.b64 t2,{%2,%3};\n\t"
        "mul.rn.f32x2 ax,t2,%4;\n\t"
        "and.b64 ax,ax,%5;\n\t"
        "fma.rn.f32x2 d,ax,%6,%7;\n\t"
        "fma.rn.f32x2 d,d,ax,%8;\n\t"
        "fma.rn.f32x2 d,d,ax,%9;\n\t"
        "fma.rn.f32x2 d,d,ax,%10;\n\t"
        "fma.rn.f32x2 d,d,ax,%11;\n\t"
        "fma.rn.f32x2 d,d,ax,%12;\n\t"
        "mov.b64 {dl,dh},d;\n\t"
        "rcp.approx.f32 dl,dl;\n\t"
        "rcp.approx.f32 dh,dh;\n\t"
        "mov.b64 r,{dl,dh};\n\t"
        "mul.rn.f32x2 r,r,r;\n\t"
        "mul.rn.f32x2 r,r,r;\n\t"
        "mul.rn.f32x2 r,r,r;\n\t"
        "mul.rn.f32x2 r,r,r;\n\t"
        "fma.rn.f32x2 r,r,%13,%4;\n\t"
        "mul.rn.f32x2 d,ax,r;\n\t"
        "fma.rn.f32x2 d,t2,%14,d;\n\t"
        "mov.b64 {%0,%1},d;\n\t"
        "}"
        : "=f"(olo), "=f"(ohi)
        : "f"(tlo), "f"(thi),
          "l"(g.CINV), "l"(g.ABSM), "l"(g.A6), "l"(g.A5), "l"(g.A4),
          "l"(g.A3), "l"(g.A2), "l"(g.A1), "l"(g.ONE), "l"(g.NCV), "l"(g.HALF));
}

// ---------------- misc ----------------
__device__ __forceinline__ uint32_t f2tf(float f) {
    uint32_t r; asm("cvt.rna.tf32.f32 %0, %1;" : "=r"(r) : "f"(f)); return r;
}
__device__ __forceinline__ float f2tff(float f) { return __uint_as_float(f2tf(f)); }

__device__ __forceinline__ void mma_tf32(float c[4],
                                         uint32_t a0, uint32_t a1, uint32_t a2, uint32_t a3,
                                         uint32_t b0, uint32_t b1) {
    asm volatile("mma.sync.aligned.m16n8k8.row.col.f32.tf32.tf32.f32 "
                 "{%0,%1,%2,%3}, {%4,%5,%6,%7}, {%8,%9}, {%0,%1,%2,%3};"
                 : "+f"(c[0]), "+f"(c[1]), "+f"(c[2]), "+f"(c[3])
                 : "r"(a0), "r"(a1), "r"(a2), "r"(a3), "r"(b0), "r"(b1));
}

// warp GEMM: A[m16 x 128] (swizzled smem) @ W^T; B fragments via LDG from global
// fragment-pair image [n8][k8][lane]{b0,b1} -> one LDG.64, immediate offsets.
template <int NTILES>
__device__ __forceinline__ void warp_gemm(const float* __restrict__ A,
                                          const float2* __restrict__ WF,
                                          float acc[NTILES][4],
                                          int m0, int n8base, int lr, int lc, int lane) {
    const float* ar0 = A + (m0 + lr) * 128;
    const float* ar1 = ar0 + 8 * 128;
    const float2* wb = WF + (size_t)(n8base * 16) * 32 + lane;
    const int sl = lr << 2;
    #pragma unroll
    for (int k8 = 0; k8 < 16; k8++) {
        int i0 = (k8 * 8 + lc) ^ sl;
        int i4 = i0 ^ 4;
        uint32_t a0 = __float_as_uint(ar0[i0]);
        uint32_t a1 = __float_as_uint(ar1[i0]);
        uint32_t a2 = __float_as_uint(ar0[i4]);
        uint32_t a3 = __float_as_uint(ar1[i4]);
        #pragma unroll
        for (int nt = 0; nt < NTILES; nt++) {
            float2 b = __ldg(wb + (nt * 16 + k8) * 32);
            mma_tf32(acc[nt], a0, a1, a2, a3,
                     __float_as_uint(b.x), __float_as_uint(b.y));
        }
    }
}

// ---------------- prep: weights -> tf32-rounded fragment-pair images (global) ----------------
__global__ void prep_kernel(const float* __restrict__ wn2, const float* __restrict__ we2,
                            const float* __restrict__ wc2, const float* __restrict__ wc1) {
    int stride = gridDim.x * blockDim.x;
    int t0 = blockIdx.x * blockDim.x + threadIdx.x;
    for (int i = t0; i < 128 * 64; i += stride) {
        int k = i >> 6, n = i & 63;
        int idx = (((n >> 3) * 16 + (k >> 3)) * 32 + (n & 7) * 4 + (k & 3)) * 2 + ((k >> 2) & 1);
        W_IMG[0     + idx] = f2tff(wn2[i]);
        W_IMG[8192  + idx] = f2tff(we2[i]);
        W_IMG[16384 + idx] = f2tff(wc2[i]);
    }
    for (int i = t0; i < 128 * 128; i += stride) {
        int k = i >> 7, n = i & 127;
        int idx = (((n >> 3) * 16 + (k >> 3)) * 32 + (n & 7) * 4 + (k & 3)) * 2 + ((k >> 2) & 1);
        W_IMG[24576 + idx] = f2tff(wc1[i]);
    }
}

// ---------------- main fused kernel: 3 CTAs/SM ----------------
__global__ void __launch_bounds__(NT, 3)
lifting_mma_kernel(const float* __restrict__ u0,      const float* __restrict__ x,
                   const float* __restrict__ node_w1, const float* __restrict__ node_b1,
                   const float* __restrict__ node_b2,
                   const float* __restrict__ edge_w1, const float* __restrict__ edge_b1,
                   const float* __restrict__ edge_b2,
                   const float* __restrict__ comb_b1, const float* __restrict__ comb_b2,
                   float* __restrict__ out)
{
    extern __shared__ float sm[];
    const int tid  = threadIdx.x;
    const int w    = tid >> 5;
    const int lane = tid & 31;
    const int lr   = lane >> 2, lc = lane & 3;
    const int blk  = blockIdx.x;
    const int bb   = blk / (NXV / TP);
    const int i0   = (blk % (NXV / TP)) * TP;
    const float* row_u = u0 + (size_t)bb * NXV;
    const float* row_x = x  + (size_t)bb * NXV;

    // ---- halo (clamped) ----
    for (int t = tid; t < TP + 6; t += NT) {
        int gi = i0 - 3 + t;
        gi = gi < 0 ? 0 : (gi > NXV - 1 ? NXV - 1 : gi);
        sm[S_U + t] = row_u[gi];
        sm[S_X + t] = row_x[gi];
    }
    __syncthreads();

    const GConst gc = make_gc();

    const int hh = tid & 127;       // hidden unit
    const int ph = tid >> 7;        // phase 0..1
    const int m0 = (w & 3) * 16;    // warp m-strip (4 strips)
    const int nh = w >> 2;          // warp n-half
    const int n8b  = nh * 4;        // N=64 GEMM fragment base
    const int n8b1 = nh * 8;        // N=128 GEMM fragment base
    const int nb   = nh * 32;
    const int nb1  = nh * 64;

    const float2* WFn2 = (const float2*)(W_IMG);
    const float2* WFe2 = (const float2*)(W_IMG + 8192);
    const float2* WFc2 = (const float2*)(W_IMG + 16384);
    const float2* WFc1 = (const float2*)(W_IMG + 24576);

    // ---- Stage 1: edge layer-1 (7-offset gelu sum) -> A ----
    {
        const float e0 = edge_w1[hh];
        const float e1 = edge_w1[128 + hh];
        const float e2 = edge_w1[256 + hh];
        const float eb = edge_b1[hh];
        const float e01 = e0 + e1;
        #pragma unroll 2
        for (int i = 0; i < 16; i++) {
            const int p0 = 2 * ph + 4 * i;      // pair (p0, p0+1)
            float zz[8];
            #pragma unroll
            for (int j = 0; j < 8; j += 2) {
                float2 uu = *(const float2*)(sm + S_U + p0 + j);
                float2 xx = *(const float2*)(sm + S_X + p0 + j);
                zz[j]     = fmaf(e1, uu.x, e2 * xx.x);
                zz[j + 1] = fmaf(e1, uu.y, e2 * xx.y);
            }
            float ba = fmaf(e01, sm[S_U + p0 + 3], eb) - zz[3];
            float bc = fmaf(e01, sm[S_U + p0 + 4], eb) - zz[4];
            float sAl = 0.f, sAh = 0.f, sBl = 0.f, sBh = 0.f;
            #pragma unroll
            for (int o = 0; o < 7; o++) {
                float tlo = ba + zz[o];
                float thi = bc + zz[o + 1];
                if (o & 1) gelu2_acc2(tlo, thi, sBl, sBh, gc);
                else       gelu2_acc2(tlo, thi, sAl, sAh, gc);
            }
            sm[S_A + SW(p0, hh)]     = f2tff(sAl + sBl);
            sm[S_A + SW(p0 + 1, hh)] = f2tff(sAh + sBh);
        }
    }
    __syncthreads();

    // ---- MMA edge ----
    float accE[4][4];
    #pragma unroll
    for (int i = 0; i < 4; i++) { accE[i][0]=accE[i][1]=accE[i][2]=accE[i][3]=0.f; }
    warp_gemm<4>(sm + S_A, WFe2, accE, m0, n8b, lr, lc, lane);
    __syncthreads();

    // ---- Stage 2: node layer-1 + gelu -> A ----
    {
        const float a0 = node_w1[hh];
        const float a1 = node_w1[128 + hh];
        const float nbb = node_b1[hh];
        #pragma unroll 2
        for (int i = 0; i < 16; i++) {
            const int p0 = 2 * ph + 4 * i;
            float va = fmaf(a0, sm[S_U + p0 + 3], fmaf(a1, sm[S_X + p0 + 3], nbb));
            float vb = fmaf(a0, sm[S_U + p0 + 4], fmaf(a1, sm[S_X + p0 + 4], nbb));
            float glo, ghi;
            gelu2p(va, vb, glo, ghi, gc);
            sm[S_A + SW(p0, hh)]     = f2tff(glo);
            sm[S_A + SW(p0 + 1, hh)] = f2tff(ghi);
        }
    }
    __syncthreads();

    // ---- MMA node ----
    float accN[4][4];
    #pragma unroll
    for (int i = 0; i < 4; i++) { accN[i][0]=accN[i][1]=accN[i][2]=accN[i][3]=0.f; }
    warp_gemm<4>(sm + S_A, WFn2, accN, m0, n8b, lr, lc, lane);
    __syncthreads();

    // ---- Stage 3: assemble C = [h_self + b | agg + 7b] -> A ----
    {
        float* c0 = sm + S_A + (m0 + lr) * 128;
        float* c1 = c0 + 8 * 128;
        const int sl = lr << 2;
        #pragma unroll
        for (int nt = 0; nt < 4; nt++) {
            int colx = nb + nt * 8 + lc * 2;
            int swn = colx ^ sl;
            int swe = (64 + colx) ^ sl;
            float2 bn = *(const float2*)(node_b2 + colx);
            float2 be = *(const float2*)(edge_b2 + colx);
            *(float2*)(c0 + swn) = make_float2(f2tff(accN[nt][0] + bn.x), f2tff(accN[nt][1] + bn.y));
            *(float2*)(c1 + swn) = make_float2(f2tff(accN[nt][2] + bn.x), f2tff(accN[nt][3] + bn.y));
            *(float2*)(c0 + swe) = make_float2(f2tff(fmaf(7.f, be.x, accE[nt][0])),
                                               f2tff(fmaf(7.f, be.y, accE[nt][1])));
            *(float2*)(c1 + swe) = make_float2(f2tff(fmaf(7.f, be.x, accE[nt][2])),
                                               f2tff(fmaf(7.f, be.y, accE[nt][3])));
        }
    }
    __syncthreads();

    // ---- MMA comb1 (N=128) ----
    float acc1[8][4];
    #pragma unroll
    for (int i = 0; i < 8; i++) { acc1[i][0]=acc1[i][1]=acc1[i][2]=acc1[i][3]=0.f; }
    warp_gemm<8>(sm + S_A, WFc1, acc1, m0, n8b1, lr, lc, lane);
    __syncthreads();

    // ---- Stage 4: G2 = gelu(acc1 + comb_b1) -> A ----
    {
        float* g0 = sm + S_A + (m0 + lr) * 128;
        float* g1 = g0 + 8 * 128;
        const int sl = lr << 2;
        #pragma unroll
        for (int nt = 0; nt < 8; nt++) {
            int col = nb1 + nt * 8 + lc * 2;
            int sw  = col ^ sl;
            float2 bf = *(const float2*)(comb_b1 + col);
            float r0, r1, r2, r3;
            gelu2p(acc1[nt][0] + bf.x, acc1[nt][1] + bf.y, r0, r1, gc);
            gelu2p(acc1[nt][2] + bf.x, acc1[nt][3] + bf.y, r2, r3, gc);
            *(float2*)(g0 + sw) = make_float2(f2tff(r0), f2tff(r1));
            *(float2*)(g1 + sw) = make_float2(f2tff(r2), f2tff(r3));
        }
    }
    __syncthreads();

    // ---- MMA comb2 + epilogue ----
    float acc2[4][4];
    #pragma unroll
    for (int i = 0; i < 4; i++) { acc2[i][0]=acc2[i][1]=acc2[i][2]=acc2[i][3]=0.f; }
    warp_gemm<4>(sm + S_A, WFc2, acc2, m0, n8b, lr, lc, lane);

    {
        float* orow0 = out + ((size_t)bb * NXV + i0 + m0 + lr) * 64;
        float* orow1 = orow0 + 8 * 64;
        #pragma unroll
        for (int nt = 0; nt < 4; nt++) {
            int colx = nb + nt * 8 + lc * 2;
            float2 b = *(const float2*)(comb_b2 + colx);
            *(float2*)(orow0 + colx) = make_float2(acc2[nt][0] + b.x, acc2[nt][1] + b.y);
            *(float2*)(orow1 + colx) = make_float2(acc2[nt][2] + b.x, acc2[nt][3] + b.y);
        }
    }
}

extern "C" void kernel_launch(void* const* d_in, const int* in_sizes, int n_in,
                              void* d_out, int out_size)
{
    const float* u0      = (const float*)d_in[0];
    const float* x       = (const float*)d_in[1];
    const float* node_w1 = (const float*)d_in[2];
    const float* node_b1 = (const float*)d_in[3];
    const float* node_w2 = (const float*)d_in[4];
    const float* node_b2 = (const float*)d_in[5];
    const float* edge_w1 = (const float*)d_in[6];
    const float* edge_b1 = (const float*)d_in[7];
    const float* edge_w2 = (const float*)d_in[8];
    const float* edge_b2 = (const float*)d_in[9];
    const float* comb_w1 = (const float*)d_in[10];
    const float* comb_b1 = (const float*)d_in[11];
    const float* comb_w2 = (const float*)d_in[12];
    const float* comb_b2 = (const float*)d_in[13];
    float* out = (float*)d_out;

    prep_kernel<<<48, 256>>>(node_w2, edge_w2, comb_w2, comb_w1);

    const size_t smem = SMEM_FLOATS * sizeof(float);
    cudaFuncSetAttribute(lifting_mma_kernel,
                         cudaFuncAttributeMaxDynamicSharedMemorySize, (int)smem);
    lifting_mma_kernel<<<NBLK, NT, smem>>>(u0, x,
                                           node_w1, node_b1, node_b2,
                                           edge_w1, edge_b1, edge_b2,
                                           comb_b1, comb_b2,
                                           out);
}

// round 12
// speedup vs baseline: 1.1111x; 1.1111x over previous
#include <cuda_runtime.h>
#include <cstdint>
#include <math.h>

// ---------------- problem constants ----------------
#define NXV 16384
#define BV  16
#define TP  64            // points per block
#define NT  256           // threads per block (8 warps)
#define NBLK (BV * (NXV / TP))   // 4096

// ---------------- swizzled A-tile addressing ----------------
__device__ __forceinline__ int SW(int row, int k) {
    return row * 128 + (k ^ ((row & 7) << 2));
}

// ---------------- smem layout (float offsets) ----------------
#define S_A   0                  // activation / C / G2 buffer 64 x 128 (32KB)
#define S_U   8192               // u halo (70 -> 72)
#define S_X   (S_U + 72)
#define SMEM_FLOATS (S_X + 72)   // 33344 B -> 3 CTAs/SM

#define WIMG_FLOATS 40960        // weight fragment images in GLOBAL (L1/L2-resident)
__device__ float W_IMG[WIMG_FLOATS];

typedef unsigned long long u64;

__device__ __forceinline__ u64 pk2(float lo, float hi) {
    u64 r; asm("mov.b64 %0,{%1,%2};" : "=l"(r) : "f"(lo), "f"(hi)); return r;
}

// ---------------- fast tanh-gelu (stage 1 only): s += gelu(t) packed pair ----------------
// gelu(t) = 0.5 t (1 + tanh(0.79788456 t + 0.03567741 t^3))
#define P_GC1  0x3F4C422A3F4C422AULL   // 0.79788456 x2
#define P_GC2  0x3D12220F3D12220FULL   // 0.03567741 x2 (0.79788456*0.044715)
#define P_HALFP 0x3F0000003F000000ULL  // 0.5 x2
__device__ __forceinline__ void gelu_tanh_acc2(float tlo, float thi,
                                               float& slo, float& shi) {
    asm("{\n\t"
        ".reg .b64 t2,s2,sq,q,a,h,m;\n\t"
        ".reg .f32 al,ah;\n\t"
        "mov.b64 t2,{%2,%3};\n\t"
        "mov.b64 s2,{%0,%1};\n\t"
        "mul.rn.f32x2 sq,t2,t2;\n\t"
        "fma.rn.f32x2 q,sq,%5,%4;\n\t"
        "mul.rn.f32x2 a,t2,q;\n\t"
        "mov.b64 {al,ah},a;\n\t"
        "tanh.approx.f32 al,al;\n\t"
        "tanh.approx.f32 ah,ah;\n\t"
        "mov.b64 h,{al,ah};\n\t"
        "fma.rn.f32x2 h,h,%6,%6;\n\t"
        "fma.rn.f32x2 s2,t2,h,s2;\n\t"
        "mov.b64 {%0,%1},s2;\n\t"
        "}"
        : "+f"(slo), "+f"(shi)
        : "f"(tlo), "f"(thi),
          "l"((u64)P_GC1), "l"((u64)P_GC2), "l"((u64)P_HALFP));
}

// ---------------- exact-ish gelu (A&S 7.1.28) for stages 2 & 4 ----------------
struct GConst { u64 CINV, ABSM, A6, A5, A4, A3, A2, A1, ONE, NCV, HALF; };
__device__ __forceinline__ GConst make_gc() {
    GConst g;
    g.CINV = 0x3F3504F33F3504F3ULL;
    g.ABSM = 0x7FFFFFFF7FFFFFFFULL;
    g.A6   = pk2(0.0000430638f, 0.0000430638f);
    g.A5   = pk2(0.0002765672f, 0.0002765672f);
    g.A4   = pk2(0.0001520143f, 0.0001520143f);
    g.A3   = pk2(0.0092705272f, 0.0092705272f);
    g.A2   = pk2(0.0422820123f, 0.0422820123f);
    g.A1   = pk2(0.0705230784f, 0.0705230784f);
    g.ONE  = 0x3F8000003F800000ULL;
    g.NCV  = 0xBF3504F3BF3504F3ULL;
    g.HALF = 0x3F0000003F000000ULL;
    return g;
}

__device__ __forceinline__ void gelu2p(float tlo, float thi,
                                       float& olo, float& ohi, const GConst& g) {
    asm("{\n\t"
        ".reg .b64 t2,ax,d,r;\n\t"
        ".reg .f32 dl,dh;\n\t"
        "mov.b64 t2,{%2,%3};\n\t"
        "mul.rn.f32x2 ax,t2,%4;\n\t"
        "and.b64 ax,ax,%5;\n\t"
        "fma.rn.f32x2 d,ax,%6,%7;\n\t"
        "fma.rn.f32x2 d,d,ax,%8;\n\t"
        "fma.rn.f32x2 d,d,ax,%9;\n\t"
        "fma.rn.f32x2 d,d,ax,%10;\n\t"
        "fma.rn.f32x2 d,d,ax,%11;\n\t"
        "fma.rn.f32x2 d,d,ax,%12;\n\t"
        "mov.b64 {dl,dh},d;\n\t"
        "rcp.approx.f32 dl,dl;\n\t"
        "rcp.approx.f32 dh,dh;\n\t"
        "mov.b64 r,{dl,dh};\n\t"
        "mul.rn.f32x2 r,r,r;\n\t"
        "mul.rn.f32x2 r,r,r;\n\t"
        "mul.rn.f32x2 r,r,r;\n\t"
        "mul.rn.f32x2 r,r,r;\n\t"
        "fma.rn.f32x2 r,r,%13,%4;\n\t"
        "mul.rn.f32x2 d,ax,r;\n\t"
        "fma.rn.f32x2 d,t2,%14,d;\n\t"
        "mov.b64 {%0,%1},d;\n\t"
        "}"
        : "=f"(olo), "=f"(ohi)
        : "f"(tlo), "f"(thi),
          "l"(g.CINV), "l"(g.ABSM), "l"(g.A6), "l"(g.A5), "l"(g.A4),
          "l"(g.A3), "l"(g.A2), "l"(g.A1), "l"(g.ONE), "l"(g.NCV), "l"(g.HALF));
}

// ---------------- misc ----------------
__device__ __forceinline__ uint32_t f2tf(float f) {
    uint32_t r; asm("cvt.rna.tf32.f32 %0, %1;" : "=r"(r) : "f"(f)); return r;
}
__device__ __forceinline__ float f2tff(float f) { return __uint_as_float(f2tf(f)); }

__device__ __forceinline__ void mma_tf32(float c[4],
                                         uint32_t a0, uint32_t a1, uint32_t a2, uint32_t a3,
                                         uint32_t b0, uint32_t b1) {
    asm volatile("mma.sync.aligned.m16n8k8.row.col.f32.tf32.tf32.f32 "
                 "{%0,%1,%2,%3}, {%4,%5,%6,%7}, {%8,%9}, {%0,%1,%2,%3};"
                 : "+f"(c[0]), "+f"(c[1]), "+f"(c[2]), "+f"(c[3])
                 : "r"(a0), "r"(a1), "r"(a2), "r"(a3), "r"(b0), "r"(b1));
}

// warp GEMM: A swizzled smem; B fragments via LDG.64 from global fragment image
template <int NTILES>
__device__ __forceinline__ void warp_gemm(const float* __restrict__ A,
                                          const float2* __restrict__ WF,
                                          float acc[NTILES][4],
                                          int m0, int n8base, int lr, int lc, int lane) {
    const float* ar0 = A + (m0 + lr) * 128;
    const float* ar1 = ar0 + 8 * 128;
    const float2* wb = WF + (size_t)(n8base * 16) * 32 + lane;
    const int sl = lr << 2;
    #pragma unroll
    for (int k8 = 0; k8 < 16; k8++) {
        int i0 = (k8 * 8 + lc) ^ sl;
        int i4 = i0 ^ 4;
        uint32_t a0 = __float_as_uint(ar0[i0]);
        uint32_t a1 = __float_as_uint(ar1[i0]);
        uint32_t a2 = __float_as_uint(ar0[i4]);
        uint32_t a3 = __float_as_uint(ar1[i4]);
        #pragma unroll
        for (int nt = 0; nt < NTILES; nt++) {
            float2 b = __ldg(wb + (nt * 16 + k8) * 32);
            mma_tf32(acc[nt], a0, a1, a2, a3,
                     __float_as_uint(b.x), __float_as_uint(b.y));
        }
    }
}

// ---------------- prep: weights -> tf32-rounded fragment-pair images ----------------
__global__ void prep_kernel(const float* __restrict__ wn2, const float* __restrict__ we2,
                            const float* __restrict__ wc2, const float* __restrict__ wc1) {
    int stride = gridDim.x * blockDim.x;
    int t0 = blockIdx.x * blockDim.x + threadIdx.x;
    for (int i = t0; i < 128 * 64; i += stride) {
        int k = i >> 6, n = i & 63;
        int idx = (((n >> 3) * 16 + (k >> 3)) * 32 + (n & 7) * 4 + (k & 3)) * 2 + ((k >> 2) & 1);
        W_IMG[0     + idx] = f2tff(wn2[i]);
        W_IMG[8192  + idx] = f2tff(we2[i]);
        W_IMG[16384 + idx] = f2tff(wc2[i]);
    }
    for (int i = t0; i < 128 * 128; i += stride) {
        int k = i >> 7, n = i & 127;
        int idx = (((n >> 3) * 16 + (k >> 3)) * 32 + (n & 7) * 4 + (k & 3)) * 2 + ((k >> 2) & 1);
        W_IMG[24576 + idx] = f2tff(wc1[i]);
    }
}

// ---------------- main fused kernel: 3 CTAs/SM ----------------
__global__ void __launch_bounds__(NT, 3)
lifting_mma_kernel(const float* __restrict__ u0,      const float* __restrict__ x,
                   const float* __restrict__ node_w1, const float* __restrict__ node_b1,
                   const float* __restrict__ node_b2,
                   const float* __restrict__ edge_w1, const float* __restrict__ edge_b1,
                   const float* __restrict__ edge_b2,
                   const float* __restrict__ comb_b1, const float* __restrict__ comb_b2,
                   float* __restrict__ out)
{
    extern __shared__ float sm[];
    const int tid  = threadIdx.x;
    const int w    = tid >> 5;
    const int lane = tid & 31;
    const int lr   = lane >> 2, lc = lane & 3;
    const int blk  = blockIdx.x;
    const int bb   = blk / (NXV / TP);
    const int i0   = (blk % (NXV / TP)) * TP;
    const float* row_u = u0 + (size_t)bb * NXV;
    const float* row_x = x  + (size_t)bb * NXV;

    // ---- halo (clamped) ----
    for (int t = tid; t < TP + 6; t += NT) {
        int gi = i0 - 3 + t;
        gi = gi < 0 ? 0 : (gi > NXV - 1 ? NXV - 1 : gi);
        sm[S_U + t] = row_u[gi];
        sm[S_X + t] = row_x[gi];
    }
    __syncthreads();

    const GConst gc = make_gc();

    const int hh = tid & 127;       // hidden unit
    const int ph = tid >> 7;        // phase 0..1
    const int m0 = (w & 3) * 16;    // warp m-strip
    const int nh = w >> 2;          // warp n-half
    const int n8b  = nh * 4;
    const int n8b1 = nh * 8;
    const int nb   = nh * 32;
    const int nb1  = nh * 64;

    const float2* WFn2 = (const float2*)(W_IMG);
    const float2* WFe2 = (const float2*)(W_IMG + 8192);
    const float2* WFc2 = (const float2*)(W_IMG + 16384);
    const float2* WFc1 = (const float2*)(W_IMG + 24576);

    // ---- Stage 1: edge layer-1 (7-offset gelu sum, tanh-gelu) -> A ----
    {
        const float e0 = edge_w1[hh];
        const float e1 = edge_w1[128 + hh];
        const float e2 = edge_w1[256 + hh];
        const float eb = edge_b1[hh];
        const float e01 = e0 + e1;
        #pragma unroll 2
        for (int i = 0; i < 16; i++) {
            const int p0 = 2 * ph + 4 * i;      // pair (p0, p0+1)
            float zz[8];
            #pragma unroll
            for (int j = 0; j < 8; j += 2) {
                float2 uu = *(const float2*)(sm + S_U + p0 + j);
                float2 xx = *(const float2*)(sm + S_X + p0 + j);
                zz[j]     = fmaf(e1, uu.x, e2 * xx.x);
                zz[j + 1] = fmaf(e1, uu.y, e2 * xx.y);
            }
            float ba = fmaf(e01, sm[S_U + p0 + 3], eb) - zz[3];
            float bc = fmaf(e01, sm[S_U + p0 + 4], eb) - zz[4];
            float sAl = 0.f, sAh = 0.f, sBl = 0.f, sBh = 0.f;  // 2 chains for ILP
            #pragma unroll
            for (int o = 0; o < 7; o++) {
                float tlo = ba + zz[o];
                float thi = bc + zz[o + 1];
                if (o & 1) gelu_tanh_acc2(tlo, thi, sBl, sBh);
                else       gelu_tanh_acc2(tlo, thi, sAl, sAh);
            }
            sm[S_A + SW(p0, hh)]     = f2tff(sAl + sBl);
            sm[S_A + SW(p0 + 1, hh)] = f2tff(sAh + sBh);
        }
    }
    __syncthreads();

    // ---- MMA edge ----
    float accE[4][4];
    #pragma unroll
    for (int i = 0; i < 4; i++) { accE[i][0]=accE[i][1]=accE[i][2]=accE[i][3]=0.f; }
    warp_gemm<4>(sm + S_A, WFe2, accE, m0, n8b, lr, lc, lane);
    __syncthreads();

    // ---- Stage 2: node layer-1 + gelu (A&S erf) -> A ----
    {
        const float a0 = node_w1[hh];
        const float a1 = node_w1[128 + hh];
        const float nbb = node_b1[hh];
        #pragma unroll 2
        for (int i = 0; i < 16; i++) {
            const int p0 = 2 * ph + 4 * i;
            float va = fmaf(a0, sm[S_U + p0 + 3], fmaf(a1, sm[S_X + p0 + 3], nbb));
            float vb = fmaf(a0, sm[S_U + p0 + 4], fmaf(a1, sm[S_X + p0 + 4], nbb));
            float glo, ghi;
            gelu2p(va, vb, glo, ghi, gc);
            sm[S_A + SW(p0, hh)]     = f2tff(glo);
            sm[S_A + SW(p0 + 1, hh)] = f2tff(ghi);
        }
    }
    __syncthreads();

    // ---- MMA node ----
    float accN[4][4];
    #pragma unroll
    for (int i = 0; i < 4; i++) { accN[i][0]=accN[i][1]=accN[i][2]=accN[i][3]=0.f; }
    warp_gemm<4>(sm + S_A, WFn2, accN, m0, n8b, lr, lc, lane);
    __syncthreads();

    // ---- Stage 3: assemble C = [h_self + b | agg + 7b] -> A ----
    {
        float* c0 = sm + S_A + (m0 + lr) * 128;
        float* c1 = c0 + 8 * 128;
        const int sl = lr << 2;
        #pragma unroll
        for (int nt = 0; nt < 4; nt++) {
            int colx = nb + nt * 8 + lc * 2;
            int swn = colx ^ sl;
            int swe = (64 + colx) ^ sl;
            float2 bn = *(const float2*)(node_b2 + colx);
            float2 be = *(const float2*)(edge_b2 + colx);
            *(float2*)(c0 + swn) = make_float2(f2tff(accN[nt][0] + bn.x), f2tff(accN[nt][1] + bn.y));
            *(float2*)(c1 + swn) = make_float2(f2tff(accN[nt][2] + bn.x), f2tff(accN[nt][3] + bn.y));
            *(float2*)(c0 + swe) = make_float2(f2tff(fmaf(7.f, be.x, accE[nt][0])),
                                               f2tff(fmaf(7.f, be.y, accE[nt][1])));
            *(float2*)(c1 + swe) = make_float2(f2tff(fmaf(7.f, be.x, accE[nt][2])),
                                               f2tff(fmaf(7.f, be.y, accE[nt][3])));
        }
    }
    __syncthreads();

    // ---- MMA comb1 (N=128) ----
    float acc1[8][4];
    #pragma unroll
    for (int i = 0; i < 8; i++) { acc1[i][0]=acc1[i][1]=acc1[i][2]=acc1[i][3]=0.f; }
    warp_gemm<8>(sm + S_A, WFc1, acc1, m0, n8b1, lr, lc, lane);
    __syncthreads();

    // ---- Stage 4: G2 = gelu(acc1 + comb_b1) (A&S erf) -> A ----
    {
        float* g0 = sm + S_A + (m0 + lr) * 128;
        float* g1 = g0 + 8 * 128;
        const int sl = lr << 2;
        #pragma unroll
        for (int nt = 0; nt < 8; nt++) {
            int col = nb1 + nt * 8 + lc * 2;
            int sw  = col ^ sl;
            float2 bf = *(const float2*)(comb_b1 + col);
            float r0, r1, r2, r3;
            gelu2p(acc1[nt][0] + bf.x, acc1[nt][1] + bf.y, r0, r1, gc);
            gelu2p(acc1[nt][2] + bf.x, acc1[nt][3] + bf.y, r2, r3, gc);
            *(float2*)(g0 + sw) = make_float2(f2tff(r0), f2tff(r1));
            *(float2*)(g1 + sw) = make_float2(f2tff(r2), f2tff(r3));
        }
    }
    __syncthreads();

    // ---- MMA comb2 + epilogue ----
    float acc2[4][4];
    #pragma unroll
    for (int i = 0; i < 4; i++) { acc2[i][0]=acc2[i][1]=acc2[i][2]=acc2[i][3]=0.f; }
    warp_gemm<4>(sm + S_A, WFc2, acc2, m0, n8b, lr, lc, lane);

    {
        float* orow0 = out + ((size_t)bb * NXV + i0 + m0 + lr) * 64;
        float* orow1 = orow0 + 8 * 64;
        #pragma unroll
        for (int nt = 0; nt < 4; nt++) {
            int colx = nb + nt * 8 + lc * 2;
            float2 b = *(const float2*)(comb_b2 + colx);
            *(float2*)(orow0 + colx) = make_float2(acc2[nt][0] + b.x, acc2[nt][1] + b.y);
            *(float2*)(orow1 + colx) = make_float2(acc2[nt][2] + b.x, acc2[nt][3] + b.y);
        }
    }
}

extern "C" void kernel_launch(void* const* d_in, const int* in_sizes, int n_in,
                              void* d_out, int out_size)
{
    const float* u0      = (const float*)d_in[0];
    const float* x       = (const float*)d_in[1];
    const float* node_w1 = (const float*)d_in[2];
    const float* node_b1 = (const float*)d_in[3];
    const float* node_w2 = (const float*)d_in[4];
    const float* node_b2 = (const float*)d_in[5];
    const float* edge_w1 = (const float*)d_in[6];
    const float* edge_b1 = (const float*)d_in[7];
    const float* edge_w2 = (const float*)d_in[8];
    const float* edge_b2 = (const float*)d_in[9];
    const float* comb_w1 = (const float*)d_in[10];
    const float* comb_b1 = (const float*)d_in[11];
    const float* comb_w2 = (const float*)d_in[12];
    const float* comb_b2 = (const float*)d_in[13];
    float* out = (float*)d_out;

    prep_kernel<<<48, 256>>>(node_w2, edge_w2, comb_w2, comb_w1);

    const size_t smem = SMEM_FLOATS * sizeof(float);
    cudaFuncSetAttribute(lifting_mma_kernel,
                         cudaFuncAttributeMaxDynamicSharedMemorySize, (int)smem);
    lifting_mma_kernel<<<NBLK, NT, smem>>>(u0, x,
                                           node_w1, node_b1, node_b2,
                                           edge_w1, edge_b1, edge_b2,
                                           comb_b1, comb_b2,
                                           out);
}

// round 14
// speedup vs baseline: 1.5543x; 1.3989x over previous
#include <cuda_runtime.h>
#include <cstdint>
#include <math.h>

// ---------------- problem constants ----------------
#define NXV 16384
#define BV  16
#define TP  64            // points per block
#define NT  256           // threads per block (8 warps)
#define NBLK (BV * (NXV / TP))   // 4096

// ---------------- swizzled A-tile addressing ----------------
__device__ __forceinline__ int SW(int row, int k) {
    return row * 128 + (k ^ ((row & 7) << 2));
}

// ---------------- smem layout (float offsets) ----------------
#define S_A   0                  // activation / C / G2 buffer 64 x 128 (32KB)
#define S_U   8192               // u halo (70 -> 72)
#define S_X   (S_U + 72)
#define SMEM_FLOATS (S_X + 72)   // 33344 B -> 3 CTAs/SM

#define WIMG_FLOATS 40960        // weight fragment images in GLOBAL (L1/L2-resident)
__device__ __align__(16) float W_IMG[WIMG_FLOATS];

typedef unsigned long long u64;

__device__ __forceinline__ u64 pk2(float lo, float hi) {
    u64 r; asm("mov.b64 %0,{%1,%2};" : "=l"(r) : "f"(lo), "f"(hi)); return r;
}

// ---------------- tanh-gelu (stages 1 & 2) ----------------
// gelu(t) = 0.5 t (1 + tanh(0.79788456 t + 0.03567741 t^3))
#define P_GC1  0x3F4C422A3F4C422AULL   // 0.79788456 x2
#define P_GC2  0x3D12220F3D12220FULL   // 0.03567741 x2
#define P_HALFP 0x3F0000003F000000ULL  // 0.5 x2
__device__ __forceinline__ void gelu_tanh_acc2(float tlo, float thi,
                                               float& slo, float& shi) {
    asm("{\n\t"
        ".reg .b64 t2,s2,sq,q,a,h;\n\t"
        ".reg .f32 al,ah;\n\t"
        "mov.b64 t2,{%2,%3};\n\t"
        "mov.b64 s2,{%0,%1};\n\t"
        "mul.rn.f32x2 sq,t2,t2;\n\t"
        "fma.rn.f32x2 q,sq,%5,%4;\n\t"
        "mul.rn.f32x2 a,t2,q;\n\t"
        "mov.b64 {al,ah},a;\n\t"
        "tanh.approx.f32 al,al;\n\t"
        "tanh.approx.f32 ah,ah;\n\t"
        "mov.b64 h,{al,ah};\n\t"
        "fma.rn.f32x2 h,h,%6,%6;\n\t"
        "fma.rn.f32x2 s2,t2,h,s2;\n\t"
        "mov.b64 {%0,%1},s2;\n\t"
        "}"
        : "+f"(slo), "+f"(shi)
        : "f"(tlo), "f"(thi),
          "l"((u64)P_GC1), "l"((u64)P_GC2), "l"((u64)P_HALFP));
}
__device__ __forceinline__ void gelu_tanh2p(float tlo, float thi,
                                            float& olo, float& ohi) {
    asm("{\n\t"
        ".reg .b64 t2,sq,q,a,h;\n\t"
        ".reg .f32 al,ah;\n\t"
        "mov.b64 t2,{%2,%3};\n\t"
        "mul.rn.f32x2 sq,t2,t2;\n\t"
        "fma.rn.f32x2 q,sq,%5,%4;\n\t"
        "mul.rn.f32x2 a,t2,q;\n\t"
        "mov.b64 {al,ah},a;\n\t"
        "tanh.approx.f32 al,al;\n\t"
        "tanh.approx.f32 ah,ah;\n\t"
        "mov.b64 h,{al,ah};\n\t"
        "fma.rn.f32x2 h,h,%6,%6;\n\t"
        "mul.rn.f32x2 h,t2,h;\n\t"
        "mov.b64 {%0,%1},h;\n\t"
        "}"
        : "=f"(olo), "=f"(ohi)
        : "f"(tlo), "f"(thi),
          "l"((u64)P_GC1), "l"((u64)P_GC2), "l"((u64)P_HALFP));
}

// ---------------- A&S 7.1.28 erf-gelu (stage 4, tighter) ----------------
struct GConst { u64 CINV, ABSM, A6, A5, A4, A3, A2, A1, ONE, NCV, HALF; };
__device__ __forceinline__ GConst make_gc() {
    GConst g;
    g.CINV = 0x3F3504F33F3504F3ULL;
    g.ABSM = 0x7FFFFFFF7FFFFFFFULL;
    g.A6   = pk2(0.0000430638f, 0.0000430638f);
    g.A5   = pk2(0.0002765672f, 0.0002765672f);
    g.A4   = pk2(0.0001520143f, 0.0001520143f);
    g.A3   = pk2(0.0092705272f, 0.0092705272f);
    g.A2   = pk2(0.0422820123f, 0.0422820123f);
    g.A1   = pk2(0.0705230784f, 0.0705230784f);
    g.ONE  = 0x3F8000003F800000ULL;
    g.NCV  = 0xBF3504F3BF3504F3ULL;
    g.HALF = 0x3F0000003F000000ULL;
    return g;
}
__device__ __forceinline__ void gelu2p(float tlo, float thi,
                                       float& olo, float& ohi, const GConst& g) {
    asm("{\n\t"
        ".reg .b64 t2,ax,d,r;\n\t"
        ".reg .f32 dl,dh;\n\t"
        "mov.b64 t2,{%2,%3};\n\t"
        "mul.rn.f32x2 ax,t2,%4;\n\t"
        "and.b64 ax,ax,%5;\n\t"
        "fma.rn.f32x2 d,ax,%6,%7;\n\t"
        "fma.rn.f32x2 d,d,ax,%8;\n\t"
        "fma.rn.f32x2 d,d,ax,%9;\n\t"
        "fma.rn.f32x2 d,d,ax,%10;\n\t"
        "fma.rn.f32x2 d,d,ax,%11;\n\t"
        "fma.rn.f32x2 d,d,ax,%12;\n\t"
        "mov.b64 {dl,dh},d;\n\t"
        "rcp.approx.f32 dl,dl;\n\t"
        "rcp.approx.f32 dh,dh;\n\t"
        "mov.b64 r,{dl,dh};\n\t"
        "mul.rn.f32x2 r,r,r;\n\t"
        "mul.rn.f32x2 r,r,r;\n\t"
        "mul.rn.f32x2 r,r,r;\n\t"
        "mul.rn.f32x2 r,r,r;\n\t"
        "fma.rn.f32x2 r,r,%13,%4;\n\t"
        "mul.rn.f32x2 d,ax,r;\n\t"
        "fma.rn.f32x2 d,t2,%14,d;\n\t"
        "mov.b64 {%0,%1},d;\n\t"
        "}"
        : "=f"(olo), "=f"(ohi)
        : "f"(tlo), "f"(thi),
          "l"(g.CINV), "l"(g.ABSM), "l"(g.A6), "l"(g.A5), "l"(g.A4),
          "l"(g.A3), "l"(g.A2), "l"(g.A1), "l"(g.ONE), "l"(g.NCV), "l"(g.HALF));
}

// ---------------- misc ----------------
__device__ __forceinline__ uint32_t f2tf(float f) {
    uint32_t r; asm("cvt.rna.tf32.f32 %0, %1;" : "=r"(r) : "f"(f)); return r;
}
__device__ __forceinline__ float f2tff(float f) { return __uint_as_float(f2tf(f)); }

__device__ __forceinline__ void mma_tf32(float c[4],
                                         uint32_t a0, uint32_t a1, uint32_t a2, uint32_t a3,
                                         uint32_t b0, uint32_t b1) {
    asm volatile("mma.sync.aligned.m16n8k8.row.col.f32.tf32.tf32.f32 "
                 "{%0,%1,%2,%3}, {%4,%5,%6,%7}, {%8,%9}, {%0,%1,%2,%3};"
                 : "+f"(c[0]), "+f"(c[1]), "+f"(c[2]), "+f"(c[3])
                 : "r"(a0), "r"(a1), "r"(a2), "r"(a3), "r"(b0), "r"(b1));
}

// warp GEMM v2: B fragments via LDG.128 k8-PAIRS from global image
// image layout: [n8][kp(8)][lane] float4 {b0(k8=2kp),b1(2kp),b0(2kp+1),b1(2kp+1)}
// per kp: NTILES independent LDG.128s front-loaded, then 2*NTILES mmas.
template <int NTILES>
__device__ __forceinline__ void warp_gemm(const float* __restrict__ A,
                                          const float4* __restrict__ WF,
                                          float acc[NTILES][4],
                                          int m0, int n8base, int lr, int lc, int lane) {
    const float* ar0 = A + (m0 + lr) * 128;
    const float* ar1 = ar0 + 8 * 128;
    const float4* wb = WF + (size_t)(n8base * 8) * 32 + lane;
    const int sl = lr << 2;
    #pragma unroll
    for (int kp = 0; kp < 8; kp++) {
        float4 b[NTILES];
        #pragma unroll
        for (int nt = 0; nt < NTILES; nt++)
            b[nt] = __ldg(wb + (nt * 8 + kp) * 32);
        // k8 = 2kp
        int i0 = (kp * 16 + lc) ^ sl;
        int i4 = i0 ^ 4;
        uint32_t a0 = __float_as_uint(ar0[i0]);
        uint32_t a1 = __float_as_uint(ar1[i0]);
        uint32_t a2 = __float_as_uint(ar0[i4]);
        uint32_t a3 = __float_as_uint(ar1[i4]);
        // k8 = 2kp+1
        int j0 = (kp * 16 + 8 + lc) ^ sl;
        int j4 = j0 ^ 4;
        uint32_t c0 = __float_as_uint(ar0[j0]);
        uint32_t c1 = __float_as_uint(ar1[j0]);
        uint32_t c2 = __float_as_uint(ar0[j4]);
        uint32_t c3 = __float_as_uint(ar1[j4]);
        #pragma unroll
        for (int nt = 0; nt < NTILES; nt++)
            mma_tf32(acc[nt], a0, a1, a2, a3,
                     __float_as_uint(b[nt].x), __float_as_uint(b[nt].y));
        #pragma unroll
        for (int nt = 0; nt < NTILES; nt++)
            mma_tf32(acc[nt], c0, c1, c2, c3,
                     __float_as_uint(b[nt].z), __float_as_uint(b[nt].w));
    }
}

// ---------------- prep: weights -> tf32-rounded k8-pair fragment images ----------------
// element (k, n): float index =
//   (((n>>3)*8 + (k>>4))*32 + (n&7)*4 + (k&3)) * 4 + ((k>>3)&1)*2 + ((k>>2)&1)
__device__ __forceinline__ int frag_idx(int k, int n) {
    return ((((n >> 3) * 8 + (k >> 4)) * 32 + (n & 7) * 4 + (k & 3)) << 2)
           + (((k >> 3) & 1) << 1) + ((k >> 2) & 1);
}
__global__ void prep_kernel(const float* __restrict__ wn2, const float* __restrict__ we2,
                            const float* __restrict__ wc2, const float* __restrict__ wc1) {
    int stride = gridDim.x * blockDim.x;
    int t0 = blockIdx.x * blockDim.x + threadIdx.x;
    for (int i = t0; i < 128 * 64; i += stride) {
        int k = i >> 6, n = i & 63;
        int idx = frag_idx(k, n);
        W_IMG[0     + idx] = f2tff(wn2[i]);
        W_IMG[8192  + idx] = f2tff(we2[i]);
        W_IMG[16384 + idx] = f2tff(wc2[i]);
    }
    for (int i = t0; i < 128 * 128; i += stride) {
        int k = i >> 7, n = i & 127;
        W_IMG[24576 + frag_idx(k, n)] = f2tff(wc1[i]);
    }
}

// ---------------- main fused kernel: 3 CTAs/SM ----------------
__global__ void __launch_bounds__(NT, 3)
lifting_mma_kernel(const float* __restrict__ u0,      const float* __restrict__ x,
                   const float* __restrict__ node_w1, const float* __restrict__ node_b1,
                   const float* __restrict__ node_b2,
                   const float* __restrict__ edge_w1, const float* __restrict__ edge_b1,
                   const float* __restrict__ edge_b2,
                   const float* __restrict__ comb_b1, const float* __restrict__ comb_b2,
                   float* __restrict__ out)
{
    extern __shared__ float sm[];
    const int tid  = threadIdx.x;
    const int w    = tid >> 5;
    const int lane = tid & 31;
    const int lr   = lane >> 2, lc = lane & 3;
    const int blk  = blockIdx.x;
    const int bb   = blk / (NXV / TP);
    const int i0   = (blk % (NXV / TP)) * TP;
    const float* row_u = u0 + (size_t)bb * NXV;
    const float* row_x = x  + (size_t)bb * NXV;

    // ---- halo (clamped) ----
    for (int t = tid; t < TP + 6; t += NT) {
        int gi = i0 - 3 + t;
        gi = gi < 0 ? 0 : (gi > NXV - 1 ? NXV - 1 : gi);
        sm[S_U + t] = row_u[gi];
        sm[S_X + t] = row_x[gi];
    }
    __syncthreads();

    const GConst gc = make_gc();

    const int hh = tid & 127;       // hidden unit
    const int ph = tid >> 7;        // phase 0..1
    const int m0 = (w & 3) * 16;    // warp m-strip
    const int nh = w >> 2;          // warp n-half
    const int n8b  = nh * 4;
    const int n8b1 = nh * 8;
    const int nb   = nh * 32;
    const int nb1  = nh * 64;

    const float4* WFn2 = (const float4*)(W_IMG);
    const float4* WFe2 = (const float4*)(W_IMG + 8192);
    const float4* WFc2 = (const float4*)(W_IMG + 16384);
    const float4* WFc1 = (const float4*)(W_IMG + 24576);

    // ---- Stage 1: edge layer-1 (7-offset tanh-gelu sum) -> A ----
    {
        const float e0 = edge_w1[hh];
        const float e1 = edge_w1[128 + hh];
        const float e2 = edge_w1[256 + hh];
        const float eb = edge_b1[hh];
        const float e01 = e0 + e1;
        #pragma unroll 2
        for (int i = 0; i < 16; i++) {
            const int p0 = 2 * ph + 4 * i;
            float zz[8];
            #pragma unroll
            for (int j = 0; j < 8; j += 2) {
                float2 uu = *(const float2*)(sm + S_U + p0 + j);
                float2 xx = *(const float2*)(sm + S_X + p0 + j);
                zz[j]     = fmaf(e1, uu.x, e2 * xx.x);
                zz[j + 1] = fmaf(e1, uu.y, e2 * xx.y);
            }
            float ba = fmaf(e01, sm[S_U + p0 + 3], eb) - zz[3];
            float bc = fmaf(e01, sm[S_U + p0 + 4], eb) - zz[4];
            float sAl = 0.f, sAh = 0.f, sBl = 0.f, sBh = 0.f;
            #pragma unroll
            for (int o = 0; o < 7; o++) {
                float tlo = ba + zz[o];
                float thi = bc + zz[o + 1];
                if (o & 1) gelu_tanh_acc2(tlo, thi, sBl, sBh);
                else       gelu_tanh_acc2(tlo, thi, sAl, sAh);
            }
            sm[S_A + SW(p0, hh)]     = f2tff(sAl + sBl);
            sm[S_A + SW(p0 + 1, hh)] = f2tff(sAh + sBh);
        }
    }
    __syncthreads();

    // ---- MMA edge ----
    float accE[4][4];
    #pragma unroll
    for (int i = 0; i < 4; i++) { accE[i][0]=accE[i][1]=accE[i][2]=accE[i][3]=0.f; }
    warp_gemm<4>(sm + S_A, WFe2, accE, m0, n8b, lr, lc, lane);
    __syncthreads();

    // ---- Stage 2: node layer-1 + tanh-gelu -> A ----
    {
        const float a0 = node_w1[hh];
        const float a1 = node_w1[128 + hh];
        const float nbb = node_b1[hh];
        #pragma unroll 2
        for (int i = 0; i < 16; i++) {
            const int p0 = 2 * ph + 4 * i;
            float va = fmaf(a0, sm[S_U + p0 + 3], fmaf(a1, sm[S_X + p0 + 3], nbb));
            float vb = fmaf(a0, sm[S_U + p0 + 4], fmaf(a1, sm[S_X + p0 + 4], nbb));
            float glo, ghi;
            gelu_tanh2p(va, vb, glo, ghi);
            sm[S_A + SW(p0, hh)]     = f2tff(glo);
            sm[S_A + SW(p0 + 1, hh)] = f2tff(ghi);
        }
    }
    __syncthreads();

    // ---- MMA node ----
    float accN[4][4];
    #pragma unroll
    for (int i = 0; i < 4; i++) { accN[i][0]=accN[i][1]=accN[i][2]=accN[i][3]=0.f; }
    warp_gemm<4>(sm + S_A, WFn2, accN, m0, n8b, lr, lc, lane);
    __syncthreads();

    // ---- Stage 3: assemble C = [h_self + b | agg + 7b] -> A ----
    {
        float* c0 = sm + S_A + (m0 + lr) * 128;
        float* c1 = c0 + 8 * 128;
        const int sl = lr << 2;
        #pragma unroll
        for (int nt = 0; nt < 4; nt++) {
            int colx = nb + nt * 8 + lc * 2;
            int swn = colx ^ sl;
            int swe = (64 + colx) ^ sl;
            float2 bn = *(const float2*)(node_b2 + colx);
            float2 be = *(const float2*)(edge_b2 + colx);
            *(float2*)(c0 + swn) = make_float2(f2tff(accN[nt][0] + bn.x), f2tff(accN[nt][1] + bn.y));
            *(float2*)(c1 + swn) = make_float2(f2tff(accN[nt][2] + bn.x), f2tff(accN[nt][3] + bn.y));
            *(float2*)(c0 + swe) = make_float2(f2tff(fmaf(7.f, be.x, accE[nt][0])),
                                               f2tff(fmaf(7.f, be.y, accE[nt][1])));
            *(float2*)(c1 + swe) = make_float2(f2tff(fmaf(7.f, be.x, accE[nt][2])),
                                               f2tff(fmaf(7.f, be.y, accE[nt][3])));
        }
    }
    __syncthreads();

    // ---- MMA comb1 (N=128, two half-calls to bound registers) ----
    float acc1a[4][4], acc1b[4][4];
    #pragma unroll
    for (int i = 0; i < 4; i++) {
        acc1a[i][0]=acc1a[i][1]=acc1a[i][2]=acc1a[i][3]=0.f;
        acc1b[i][0]=acc1b[i][1]=acc1b[i][2]=acc1b[i][3]=0.f;
    }
    warp_gemm<4>(sm + S_A, WFc1, acc1a, m0, n8b1,     lr, lc, lane);
    warp_gemm<4>(sm + S_A, WFc1, acc1b, m0, n8b1 + 4, lr, lc, lane);
    __syncthreads();

    // ---- Stage 4: G2 = gelu(acc1 + comb_b1) (A&S erf) -> A ----
    {
        float* g0 = sm + S_A + (m0 + lr) * 128;
        float* g1 = g0 + 8 * 128;
        const int sl = lr << 2;
        #pragma unroll
        for (int nt = 0; nt < 8; nt++) {
            const float (*ac)[4] = (nt < 4) ? acc1a : acc1b;
            int ntl = nt & 3;
            int col = nb1 + nt * 8 + lc * 2;
            int sw  = col ^ sl;
            float2 bf = *(const float2*)(comb_b1 + col);
            float r0, r1, r2, r3;
            gelu2p(ac[ntl][0] + bf.x, ac[ntl][1] + bf.y, r0, r1, gc);
            gelu2p(ac[ntl][2] + bf.x, ac[ntl][3] + bf.y, r2, r3, gc);
            *(float2*)(g0 + sw) = make_float2(f2tff(r0), f2tff(r1));
            *(float2*)(g1 + sw) = make_float2(f2tff(r2), f2tff(r3));
        }
    }
    __syncthreads();

    // ---- MMA comb2 + epilogue ----
    float acc2[4][4];
    #pragma unroll
    for (int i = 0; i < 4; i++) { acc2[i][0]=acc2[i][1]=acc2[i][2]=acc2[i][3]=0.f; }
    warp_gemm<4>(sm + S_A, WFc2, acc2, m0, n8b, lr, lc, lane);

    {
        float* orow0 = out + ((size_t)bb * NXV + i0 + m0 + lr) * 64;
        float* orow1 = orow0 + 8 * 64;
        #pragma unroll
        for (int nt = 0; nt < 4; nt++) {
            int colx = nb + nt * 8 + lc * 2;
            float2 b = *(const float2*)(comb_b2 + colx);
            *(float2*)(orow0 + colx) = make_float2(acc2[nt][0] + b.x, acc2[nt][1] + b.y);
            *(float2*)(orow1 + colx) = make_float2(acc2[nt][2] + b.x, acc2[nt][3] + b.y);
        }
    }
}

extern "C" void kernel_launch(void* const* d_in, const int* in_sizes, int n_in,
                              void* d_out, int out_size)
{
    const float* u0      = (const float*)d_in[0];
    const float* x       = (const float*)d_in[1];
    const float* node_w1 = (const float*)d_in[2];
    const float* node_b1 = (const float*)d_in[3];
    const float* node_w2 = (const float*)d_in[4];
    const float* node_b2 = (const float*)d_in[5];
    const float* edge_w1 = (const float*)d_in[6];
    const float* edge_b1 = (const float*)d_in[7];
    const float* edge_w2 = (const float*)d_in[8];
    const float* edge_b2 = (const float*)d_in[9];
    const float* comb_w1 = (const float*)d_in[10];
    const float* comb_b1 = (const float*)d_in[11];
    const float* comb_w2 = (const float*)d_in[12];
    const float* comb_b2 = (const float*)d_in[13];
    float* out = (float*)d_out;

    prep_kernel<<<48, 256>>>(node_w2, edge_w2, comb_w2, comb_w1);

    const size_t smem = SMEM_FLOATS * sizeof(float);
    cudaFuncSetAttribute(lifting_mma_kernel,
                         cudaFuncAttributeMaxDynamicSharedMemorySize, (int)smem);
    lifting_mma_kernel<<<NBLK, NT, smem>>>(u0, x,
                                           node_w1, node_b1, node_b2,
                                           edge_w1, edge_b1, edge_b2,
                                           comb_b1, comb_b2,
                                           out);
}

// round 15
// speedup vs baseline: 1.5847x; 1.0196x over previous
#include <cuda_runtime.h>
#include <cstdint>
#include <math.h>

// ---------------- problem constants ----------------
#define NXV 16384
#define BV  16
#define TP  128           // points per block
#define NT  256           // threads per block (8 warps)
#define NBLK (BV * (NXV / TP))   // 2048

// ---------------- swizzled A-tile addressing ----------------
__device__ __forceinline__ int SW(int row, int k) {
    return row * 128 + (k ^ ((row & 7) << 2));
}

// ---------------- smem layout (float offsets) ----------------
#define S_A   0                  // activation / C / G2 buffer 128 x 128 (64KB)
#define S_U   16384              // u halo (134 -> 136)
#define S_X   (S_U + 136)
#define SMEM_FLOATS (S_X + 136)  // 16656 floats = 66624 B -> 2 CTAs/SM

#define WIMG_FLOATS 40960        // weight fragment images in GLOBAL (L1/L2-resident)
__device__ __align__(16) float W_IMG[WIMG_FLOATS];

typedef unsigned long long u64;

__device__ __forceinline__ u64 pk2(float lo, float hi) {
    u64 r; asm("mov.b64 %0,{%1,%2};" : "=l"(r) : "f"(lo), "f"(hi)); return r;
}

// ---------------- tanh-gelu (stages 1 & 2) ----------------
#define P_GC1  0x3F4C422A3F4C422AULL   // 0.79788456 x2
#define P_GC2  0x3D12220F3D12220FULL   // 0.03567741 x2
#define P_HALFP 0x3F0000003F000000ULL  // 0.5 x2
__device__ __forceinline__ void gelu_tanh_acc2(float tlo, float thi,
                                               float& slo, float& shi) {
    asm("{\n\t"
        ".reg .b64 t2,s2,sq,q,a,h;\n\t"
        ".reg .f32 al,ah;\n\t"
        "mov.b64 t2,{%2,%3};\n\t"
        "mov.b64 s2,{%0,%1};\n\t"
        "mul.rn.f32x2 sq,t2,t2;\n\t"
        "fma.rn.f32x2 q,sq,%5,%4;\n\t"
        "mul.rn.f32x2 a,t2,q;\n\t"
        "mov.b64 {al,ah},a;\n\t"
        "tanh.approx.f32 al,al;\n\t"
        "tanh.approx.f32 ah,ah;\n\t"
        "mov.b64 h,{al,ah};\n\t"
        "fma.rn.f32x2 h,h,%6,%6;\n\t"
        "fma.rn.f32x2 s2,t2,h,s2;\n\t"
        "mov.b64 {%0,%1},s2;\n\t"
        "}"
        : "+f"(slo), "+f"(shi)
        : "f"(tlo), "f"(thi),
          "l"((u64)P_GC1), "l"((u64)P_GC2), "l"((u64)P_HALFP));
}
__device__ __forceinline__ void gelu_tanh2p(float tlo, float thi,
                                            float& olo, float& ohi) {
    asm("{\n\t"
        ".reg .b64 t2,sq,q,a,h;\n\t"
        ".reg .f32 al,ah;\n\t"
        "mov.b64 t2,{%2,%3};\n\t"
        "mul.rn.f32x2 sq,t2,t2;\n\t"
        "fma.rn.f32x2 q,sq,%5,%4;\n\t"
        "mul.rn.f32x2 a,t2,q;\n\t"
        "mov.b64 {al,ah},a;\n\t"
        "tanh.approx.f32 al,al;\n\t"
        "tanh.approx.f32 ah,ah;\n\t"
        "mov.b64 h,{al,ah};\n\t"
        "fma.rn.f32x2 h,h,%6,%6;\n\t"
        "mul.rn.f32x2 h,t2,h;\n\t"
        "mov.b64 {%0,%1},h;\n\t"
        "}"
        : "=f"(olo), "=f"(ohi)
        : "f"(tlo), "f"(thi),
          "l"((u64)P_GC1), "l"((u64)P_GC2), "l"((u64)P_HALFP));
}

// ---------------- A&S 7.1.28 erf-gelu (stage 4) ----------------
struct GConst { u64 CINV, ABSM, A6, A5, A4, A3, A2, A1, ONE, NCV, HALF; };
__device__ __forceinline__ GConst make_gc() {
    GConst g;
    g.CINV = 0x3F3504F33F3504F3ULL;
    g.ABSM = 0x7FFFFFFF7FFFFFFFULL;
    g.A6   = pk2(0.0000430638f, 0.0000430638f);
    g.A5   = pk2(0.0002765672f, 0.0002765672f);
    g.A4   = pk2(0.0001520143f, 0.0001520143f);
    g.A3   = pk2(0.0092705272f, 0.0092705272f);
    g.A2   = pk2(0.0422820123f, 0.0422820123f);
    g.A1   = pk2(0.0705230784f, 0.0705230784f);
    g.ONE  = 0x3F8000003F800000ULL;
    g.NCV  = 0xBF3504F3BF3504F3ULL;
    g.HALF = 0x3F0000003F000000ULL;
    return g;
}
__device__ __forceinline__ void gelu2p(float tlo, float thi,
                                       float& olo, float& ohi, const GConst& g) {
    asm("{\n\t"
        ".reg .b64 t2,ax,d,r;\n\t"
        ".reg .f32 dl,dh;\n\t"
        "mov.b64 t2,{%2,%3};\n\t"
        "mul.rn.f32x2 ax,t2,%4;\n\t"
        "and.b64 ax,ax,%5;\n\t"
        "fma.rn.f32x2 d,ax,%6,%7;\n\t"
        "fma.rn.f32x2 d,d,ax,%8;\n\t"
        "fma.rn.f32x2 d,d,ax,%9;\n\t"
        "fma.rn.f32x2 d,d,ax,%10;\n\t"
        "fma.rn.f32x2 d,d,ax,%11;\n\t"
        "fma.rn.f32x2 d,d,ax,%12;\n\t"
        "mov.b64 {dl,dh},d;\n\t"
        "rcp.approx.f32 dl,dl;\n\t"
        "rcp.approx.f32 dh,dh;\n\t"
        "mov.b64 r,{dl,dh};\n\t"
        "mul.rn.f32x2 r,r,r;\n\t"
        "mul.rn.f32x2 r,r,r;\n\t"
        "mul.rn.f32x2 r,r,r;\n\t"
        "mul.rn.f32x2 r,r,r;\n\t"
        "fma.rn.f32x2 r,r,%13,%4;\n\t"
        "mul.rn.f32x2 d,ax,r;\n\t"
        "fma.rn.f32x2 d,t2,%14,d;\n\t"
        "mov.b64 {%0,%1},d;\n\t"
        "}"
        : "=f"(olo), "=f"(ohi)
        : "f"(tlo), "f"(thi),
          "l"(g.CINV), "l"(g.ABSM), "l"(g.A6), "l"(g.A5), "l"(g.A4),
          "l"(g.A3), "l"(g.A2), "l"(g.A1), "l"(g.ONE), "l"(g.NCV), "l"(g.HALF));
}

// ---------------- misc ----------------
__device__ __forceinline__ uint32_t f2tf(float f) {
    uint32_t r; asm("cvt.rna.tf32.f32 %0, %1;" : "=r"(r) : "f"(f)); return r;
}
__device__ __forceinline__ float f2tff(float f) { return __uint_as_float(f2tf(f)); }

__device__ __forceinline__ void mma_tf32(float c[4],
                                         uint32_t a0, uint32_t a1, uint32_t a2, uint32_t a3,
                                         uint32_t b0, uint32_t b1) {
    asm volatile("mma.sync.aligned.m16n8k8.row.col.f32.tf32.tf32.f32 "
                 "{%0,%1,%2,%3}, {%4,%5,%6,%7}, {%8,%9}, {%0,%1,%2,%3};"
                 : "+f"(c[0]), "+f"(c[1]), "+f"(c[2]), "+f"(c[3])
                 : "r"(a0), "r"(a1), "r"(a2), "r"(a3), "r"(b0), "r"(b1));
}

// warp GEMM m32: TWO m16 strips share ONE B-fragment stream.
// B image layout: [n8][kp(8)][lane] float4 {b0(2kp),b1(2kp),b0(2kp+1),b1(2kp+1)}
template <int NTILES>
__device__ __forceinline__ void warp_gemm2(const float* __restrict__ A,
                                           const float4* __restrict__ WF,
                                           float acc[2][NTILES][4],
                                           int m0, int n8base, int lr, int lc, int lane) {
    const float* ar0 = A + (m0 + lr) * 128;        // strip0 rows lr / lr+8
    const float* ar1 = ar0 + 8 * 128;
    const float* ar2 = A + (m0 + 16 + lr) * 128;   // strip1 rows
    const float* ar3 = ar2 + 8 * 128;
    const float4* wb = WF + (size_t)(n8base * 8) * 32 + lane;
    const int sl = lr << 2;
    #pragma unroll
    for (int kp = 0; kp < 8; kp++) {
        float4 b[NTILES];
        #pragma unroll
        for (int nt = 0; nt < NTILES; nt++)
            b[nt] = __ldg(wb + (nt * 8 + kp) * 32);
        int i0 = (kp * 16 + lc) ^ sl;
        int i4 = i0 ^ 4;
        int j0 = (kp * 16 + 8 + lc) ^ sl;
        int j4 = j0 ^ 4;
        // strip0, k8 = 2kp and 2kp+1
        uint32_t a00 = __float_as_uint(ar0[i0]);
        uint32_t a01 = __float_as_uint(ar1[i0]);
        uint32_t a02 = __float_as_uint(ar0[i4]);
        uint32_t a03 = __float_as_uint(ar1[i4]);
        uint32_t a10 = __float_as_uint(ar2[i0]);
        uint32_t a11 = __float_as_uint(ar3[i0]);
        uint32_t a12 = __float_as_uint(ar2[i4]);
        uint32_t a13 = __float_as_uint(ar3[i4]);
        #pragma unroll
        for (int nt = 0; nt < NTILES; nt++) {
            mma_tf32(acc[0][nt], a00, a01, a02, a03,
                     __float_as_uint(b[nt].x), __float_as_uint(b[nt].y));
            mma_tf32(acc[1][nt], a10, a11, a12, a13,
                     __float_as_uint(b[nt].x), __float_as_uint(b[nt].y));
        }
        uint32_t c00 = __float_as_uint(ar0[j0]);
        uint32_t c01 = __float_as_uint(ar1[j0]);
        uint32_t c02 = __float_as_uint(ar0[j4]);
        uint32_t c03 = __float_as_uint(ar1[j4]);
        uint32_t c10 = __float_as_uint(ar2[j0]);
        uint32_t c11 = __float_as_uint(ar3[j0]);
        uint32_t c12 = __float_as_uint(ar2[j4]);
        uint32_t c13 = __float_as_uint(ar3[j4]);
        #pragma unroll
        for (int nt = 0; nt < NTILES; nt++) {
            mma_tf32(acc[0][nt], c00, c01, c02, c03,
                     __float_as_uint(b[nt].z), __float_as_uint(b[nt].w));
            mma_tf32(acc[1][nt], c10, c11, c12, c13,
                     __float_as_uint(b[nt].z), __float_as_uint(b[nt].w));
        }
    }
}

// ---------------- prep: weights -> tf32-rounded k8-pair fragment images ----------------
__device__ __forceinline__ int frag_idx(int k, int n) {
    return ((((n >> 3) * 8 + (k >> 4)) * 32 + (n & 7) * 4 + (k & 3)) << 2)
           + (((k >> 3) & 1) << 1) + ((k >> 2) & 1);
}
__global__ void prep_kernel(const float* __restrict__ wn2, const float* __restrict__ we2,
                            const float* __restrict__ wc2, const float* __restrict__ wc1) {
    int stride = gridDim.x * blockDim.x;
    int t0 = blockIdx.x * blockDim.x + threadIdx.x;
    for (int i = t0; i < 128 * 64; i += stride) {
        int k = i >> 6, n = i & 63;
        int idx = frag_idx(k, n);
        W_IMG[0     + idx] = f2tff(wn2[i]);
        W_IMG[8192  + idx] = f2tff(we2[i]);
        W_IMG[16384 + idx] = f2tff(wc2[i]);
    }
    for (int i = t0; i < 128 * 128; i += stride) {
        int k = i >> 7, n = i & 127;
        W_IMG[24576 + frag_idx(k, n)] = f2tff(wc1[i]);
    }
}

// ---------------- main fused kernel: 2 CTAs/SM, m32 warp tiles ----------------
__global__ void __launch_bounds__(NT, 2)
lifting_mma_kernel(const float* __restrict__ u0,      const float* __restrict__ x,
                   const float* __restrict__ node_w1, const float* __restrict__ node_b1,
                   const float* __restrict__ node_b2,
                   const float* __restrict__ edge_w1, const float* __restrict__ edge_b1,
                   const float* __restrict__ edge_b2,
                   const float* __restrict__ comb_b1, const float* __restrict__ comb_b2,
                   float* __restrict__ out)
{
    extern __shared__ float sm[];
    const int tid  = threadIdx.x;
    const int w    = tid >> 5;
    const int lane = tid & 31;
    const int lr   = lane >> 2, lc = lane & 3;
    const int blk  = blockIdx.x;
    const int bb   = blk / (NXV / TP);
    const int i0   = (blk % (NXV / TP)) * TP;
    const float* row_u = u0 + (size_t)bb * NXV;
    const float* row_x = x  + (size_t)bb * NXV;

    // ---- halo (clamped) ----
    for (int t = tid; t < TP + 6; t += NT) {
        int gi = i0 - 3 + t;
        gi = gi < 0 ? 0 : (gi > NXV - 1 ? NXV - 1 : gi);
        sm[S_U + t] = row_u[gi];
        sm[S_X + t] = row_x[gi];
    }
    __syncthreads();

    const GConst gc = make_gc();

    const int hh = tid & 127;       // hidden unit
    const int ph = tid >> 7;        // phase 0..1
    const int m0 = (w & 3) * 32;    // warp m32 tile base
    const int nh = w >> 2;          // warp n-half
    const int n8b  = nh * 4;
    const int n8b1 = nh * 8;
    const int nb   = nh * 32;
    const int nb1  = nh * 64;

    const float4* WFn2 = (const float4*)(W_IMG);
    const float4* WFe2 = (const float4*)(W_IMG + 8192);
    const float4* WFc2 = (const float4*)(W_IMG + 16384);
    const float4* WFc1 = (const float4*)(W_IMG + 24576);

    // ---- Stage 1: edge layer-1 (7-offset tanh-gelu sum) -> A ----
    {
        const float e0 = edge_w1[hh];
        const float e1 = edge_w1[128 + hh];
        const float e2 = edge_w1[256 + hh];
        const float eb = edge_b1[hh];
        const float e01 = e0 + e1;
        #pragma unroll 2
        for (int i = 0; i < 32; i++) {
            const int p0 = 2 * ph + 4 * i;      // pair (p0, p0+1), covers 0..127
            float zz[8];
            #pragma unroll
            for (int j = 0; j < 8; j += 2) {
                float2 uu = *(const float2*)(sm + S_U + p0 + j);
                float2 xx = *(const float2*)(sm + S_X + p0 + j);
                zz[j]     = fmaf(e1, uu.x, e2 * xx.x);
                zz[j + 1] = fmaf(e1, uu.y, e2 * xx.y);
            }
            float ba = fmaf(e01, sm[S_U + p0 + 3], eb) - zz[3];
            float bc = fmaf(e01, sm[S_U + p0 + 4], eb) - zz[4];
            float sAl = 0.f, sAh = 0.f, sBl = 0.f, sBh = 0.f;
            #pragma unroll
            for (int o = 0; o < 7; o++) {
                float tlo = ba + zz[o];
                float thi = bc + zz[o + 1];
                if (o & 1) gelu_tanh_acc2(tlo, thi, sBl, sBh);
                else       gelu_tanh_acc2(tlo, thi, sAl, sAh);
            }
            sm[S_A + SW(p0, hh)]     = f2tff(sAl + sBl);
            sm[S_A + SW(p0 + 1, hh)] = f2tff(sAh + sBh);
        }
    }
    __syncthreads();

    // ---- MMA edge ----
    float accE[2][4][4];
    #pragma unroll
    for (int s = 0; s < 2; s++)
        #pragma unroll
        for (int i = 0; i < 4; i++) { accE[s][i][0]=accE[s][i][1]=accE[s][i][2]=accE[s][i][3]=0.f; }
    warp_gemm2<4>(sm + S_A, WFe2, accE, m0, n8b, lr, lc, lane);
    __syncthreads();

    // ---- Stage 2: node layer-1 + tanh-gelu -> A ----
    {
        const float a0 = node_w1[hh];
        const float a1 = node_w1[128 + hh];
        const float nbb = node_b1[hh];
        #pragma unroll 2
        for (int i = 0; i < 32; i++) {
            const int p0 = 2 * ph + 4 * i;
            float va = fmaf(a0, sm[S_U + p0 + 3], fmaf(a1, sm[S_X + p0 + 3], nbb));
            float vb = fmaf(a0, sm[S_U + p0 + 4], fmaf(a1, sm[S_X + p0 + 4], nbb));
            float glo, ghi;
            gelu_tanh2p(va, vb, glo, ghi);
            sm[S_A + SW(p0, hh)]     = f2tff(glo);
            sm[S_A + SW(p0 + 1, hh)] = f2tff(ghi);
        }
    }
    __syncthreads();

    // ---- MMA node ----
    float accN[2][4][4];
    #pragma unroll
    for (int s = 0; s < 2; s++)
        #pragma unroll
        for (int i = 0; i < 4; i++) { accN[s][i][0]=accN[s][i][1]=accN[s][i][2]=accN[s][i][3]=0.f; }
    warp_gemm2<4>(sm + S_A, WFn2, accN, m0, n8b, lr, lc, lane);
    __syncthreads();

    // ---- Stage 3: assemble C = [h_self + b | agg + 7b] -> A ----
    {
        const int sl = lr << 2;
        #pragma unroll
        for (int st = 0; st < 2; st++) {
            float* c0 = sm + S_A + (m0 + st * 16 + lr) * 128;
            float* c1 = c0 + 8 * 128;
            #pragma unroll
            for (int nt = 0; nt < 4; nt++) {
                int colx = nb + nt * 8 + lc * 2;
                int swn = colx ^ sl;
                int swe = (64 + colx) ^ sl;
                float2 bn = *(const float2*)(node_b2 + colx);
                float2 be = *(const float2*)(edge_b2 + colx);
                *(float2*)(c0 + swn) = make_float2(f2tff(accN[st][nt][0] + bn.x), f2tff(accN[st][nt][1] + bn.y));
                *(float2*)(c1 + swn) = make_float2(f2tff(accN[st][nt][2] + bn.x), f2tff(accN[st][nt][3] + bn.y));
                *(float2*)(c0 + swe) = make_float2(f2tff(fmaf(7.f, be.x, accE[st][nt][0])),
                                                   f2tff(fmaf(7.f, be.y, accE[st][nt][1])));
                *(float2*)(c1 + swe) = make_float2(f2tff(fmaf(7.f, be.x, accE[st][nt][2])),
                                                   f2tff(fmaf(7.f, be.y, accE[st][nt][3])));
            }
        }
    }
    __syncthreads();

    // ---- MMA comb1 (N=128, two half-calls) ----
    float acc1a[2][4][4], acc1b[2][4][4];
    #pragma unroll
    for (int s = 0; s < 2; s++)
        #pragma unroll
        for (int i = 0; i < 4; i++) {
            acc1a[s][i][0]=acc1a[s][i][1]=acc1a[s][i][2]=acc1a[s][i][3]=0.f;
            acc1b[s][i][0]=acc1b[s][i][1]=acc1b[s][i][2]=acc1b[s][i][3]=0.f;
        }
    warp_gemm2<4>(sm + S_A, WFc1, acc1a, m0, n8b1,     lr, lc, lane);
    warp_gemm2<4>(sm + S_A, WFc1, acc1b, m0, n8b1 + 4, lr, lc, lane);
    __syncthreads();

    // ---- Stage 4: G2 = gelu(acc1 + comb_b1) (A&S erf) -> A ----
    {
        const int sl = lr << 2;
        #pragma unroll
        for (int st = 0; st < 2; st++) {
            float* g0 = sm + S_A + (m0 + st * 16 + lr) * 128;
            float* g1 = g0 + 8 * 128;
            #pragma unroll
            for (int nt = 0; nt < 8; nt++) {
                const float (*ac)[4] = (nt < 4) ? acc1a[st] : acc1b[st];
                int ntl = nt & 3;
                int col = nb1 + nt * 8 + lc * 2;
                int sw  = col ^ sl;
                float2 bf = *(const float2*)(comb_b1 + col);
                float r0, r1, r2, r3;
                gelu2p(ac[ntl][0] + bf.x, ac[ntl][1] + bf.y, r0, r1, gc);
                gelu2p(ac[ntl][2] + bf.x, ac[ntl][3] + bf.y, r2, r3, gc);
                *(float2*)(g0 + sw) = make_float2(f2tff(r0), f2tff(r1));
                *(float2*)(g1 + sw) = make_float2(f2tff(r2), f2tff(r3));
            }
        }
    }
    __syncthreads();

    // ---- MMA comb2 + epilogue ----
    float acc2[2][4][4];
    #pragma unroll
    for (int s = 0; s < 2; s++)
        #pragma unroll
        for (int i = 0; i < 4; i++) { acc2[s][i][0]=acc2[s][i][1]=acc2[s][i][2]=acc2[s][i][3]=0.f; }
    warp_gemm2<4>(sm + S_A, WFc2, acc2, m0, n8b, lr, lc, lane);

    {
        #pragma unroll
        for (int st = 0; st < 2; st++) {
            float* orow0 = out + ((size_t)bb * NXV + i0 + m0 + st * 16 + lr) * 64;
            float* orow1 = orow0 + 8 * 64;
            #pragma unroll
            for (int nt = 0; nt < 4; nt++) {
                int colx = nb + nt * 8 + lc * 2;
                float2 b = *(const float2*)(comb_b2 + colx);
                *(float2*)(orow0 + colx) = make_float2(acc2[st][nt][0] + b.x, acc2[st][nt][1] + b.y);
                *(float2*)(orow1 + colx) = make_float2(acc2[st][nt][2] + b.x, acc2[st][nt][3] + b.y);
            }
        }
    }
}

extern "C" void kernel_launch(void* const* d_in, const int* in_sizes, int n_in,
                              void* d_out, int out_size)
{
    const float* u0      = (const float*)d_in[0];
    const float* x       = (const float*)d_in[1];
    const float* node_w1 = (const float*)d_in[2];
    const float* node_b1 = (const float*)d_in[3];
    const float* node_w2 = (const float*)d_in[4];
    const float* node_b2 = (const float*)d_in[5];
    const float* edge_w1 = (const float*)d_in[6];
    const float* edge_b1 = (const float*)d_in[7];
    const float* edge_w2 = (const float*)d_in[8];
    const float* edge_b2 = (const float*)d_in[9];
    const float* comb_w1 = (const float*)d_in[10];
    const float* comb_b1 = (const float*)d_in[11];
    const float* comb_w2 = (const float*)d_in[12];
    const float* comb_b2 = (const float*)d_in[13];
    float* out = (float*)d_out;

    prep_kernel<<<48, 256>>>(node_w2, edge_w2, comb_w2, comb_w1);

    const size_t smem = SMEM_FLOATS * sizeof(float);
    cudaFuncSetAttribute(lifting_mma_kernel,
                         cudaFuncAttributeMaxDynamicSharedMemorySize, (int)smem);
    lifting_mma_kernel<<<NBLK, NT, smem>>>(u0, x,
                                           node_w1, node_b1, node_b2,
                                           edge_w1, edge_b1, edge_b2,
                                           comb_b1, comb_b2,
                                           out);
}

// round 16
// speedup vs baseline: 1.6924x; 1.0679x over previous
#include <cuda_runtime.h>
#include <cstdint>
#include <math.h>

// ---------------- problem constants ----------------
#define NXV 16384
#define BV  16
#define TP  128           // points per block
#define NT  256           // threads per block (8 warps)
#define NBLK (BV * (NXV / TP))   // 2048

// ---------------- swizzled A-tile addressing ----------------
__device__ __forceinline__ int SW(int row, int k) {
    return row * 128 + (k ^ ((row & 7) << 2));
}

// ---------------- smem layout (float offsets) ----------------
#define S_A   0                  // activation / G2 buffer 128 x 128 (64KB)
#define S_U   16384              // u halo (134 -> 136)
#define S_X   (S_U + 136)
#define SMEM_FLOATS (S_X + 136)  // 66624 B -> 2 CTAs/SM

// weight images in GLOBAL: [0]=W~n (fused node, 128x128), [16384]=W~e (fused edge),
// [32768]=Wc2 (128x64). Fused: W~n = Wn2 @ Wc1_top, W~e = We2 @ Wc1_bot.
#define WIMG_FLOATS 40960
__device__ __align__(16) float W_IMG[WIMG_FLOATS];
__device__ float BT[128];        // fused bias: node_b2@Wc1t + 7*edge_b2@Wc1b + comb_b1

typedef unsigned long long u64;

__device__ __forceinline__ u64 pk2(float lo, float hi) {
    u64 r; asm("mov.b64 %0,{%1,%2};" : "=l"(r) : "f"(lo), "f"(hi)); return r;
}

// ---------------- tanh-gelu (stages 1 & 2) ----------------
#define P_GC1  0x3F4C422A3F4C422AULL   // 0.79788456 x2
#define P_GC2  0x3D12220F3D12220FULL   // 0.03567741 x2
#define P_HALFP 0x3F0000003F000000ULL  // 0.5 x2
__device__ __forceinline__ void gelu_tanh_acc2(float tlo, float thi,
                                               float& slo, float& shi) {
    asm("{\n\t"
        ".reg .b64 t2,s2,sq,q,a,h;\n\t"
        ".reg .f32 al,ah;\n\t"
        "mov.b64 t2,{%2,%3};\n\t"
        "mov.b64 s2,{%0,%1};\n\t"
        "mul.rn.f32x2 sq,t2,t2;\n\t"
        "fma.rn.f32x2 q,sq,%5,%4;\n\t"
        "mul.rn.f32x2 a,t2,q;\n\t"
        "mov.b64 {al,ah},a;\n\t"
        "tanh.approx.f32 al,al;\n\t"
        "tanh.approx.f32 ah,ah;\n\t"
        "mov.b64 h,{al,ah};\n\t"
        "fma.rn.f32x2 h,h,%6,%6;\n\t"
        "fma.rn.f32x2 s2,t2,h,s2;\n\t"
        "mov.b64 {%0,%1},s2;\n\t"
        "}"
        : "+f"(slo), "+f"(shi)
        : "f"(tlo), "f"(thi),
          "l"((u64)P_GC1), "l"((u64)P_GC2), "l"((u64)P_HALFP));
}
__device__ __forceinline__ void gelu_tanh2p(float tlo, float thi,
                                            float& olo, float& ohi) {
    asm("{\n\t"
        ".reg .b64 t2,sq,q,a,h;\n\t"
        ".reg .f32 al,ah;\n\t"
        "mov.b64 t2,{%2,%3};\n\t"
        "mul.rn.f32x2 sq,t2,t2;\n\t"
        "fma.rn.f32x2 q,sq,%5,%4;\n\t"
        "mul.rn.f32x2 a,t2,q;\n\t"
        "mov.b64 {al,ah},a;\n\t"
        "tanh.approx.f32 al,al;\n\t"
        "tanh.approx.f32 ah,ah;\n\t"
        "mov.b64 h,{al,ah};\n\t"
        "fma.rn.f32x2 h,h,%6,%6;\n\t"
        "mul.rn.f32x2 h,t2,h;\n\t"
        "mov.b64 {%0,%1},h;\n\t"
        "}"
        : "=f"(olo), "=f"(ohi)
        : "f"(tlo), "f"(thi),
          "l"((u64)P_GC1), "l"((u64)P_GC2), "l"((u64)P_HALFP));
}

// ---------------- A&S 7.1.28 erf-gelu (stage 4) ----------------
struct GConst { u64 CINV, ABSM, A6, A5, A4, A3, A2, A1, ONE, NCV, HALF; };
__device__ __forceinline__ GConst make_gc() {
    GConst g;
    g.CINV = 0x3F3504F33F3504F3ULL;
    g.ABSM = 0x7FFFFFFF7FFFFFFFULL;
    g.A6   = pk2(0.0000430638f, 0.0000430638f);
    g.A5   = pk2(0.0002765672f, 0.0002765672f);
    g.A4   = pk2(0.0001520143f, 0.0001520143f);
    g.A3   = pk2(0.0092705272f, 0.0092705272f);
    g.A2   = pk2(0.0422820123f, 0.0422820123f);
    g.A1   = pk2(0.0705230784f, 0.0705230784f);
    g.ONE  = 0x3F8000003F800000ULL;
    g.NCV  = 0xBF3504F3BF3504F3ULL;
    g.HALF = 0x3F0000003F000000ULL;
    return g;
}
__device__ __forceinline__ void gelu2p(float tlo, float thi,
                                       float& olo, float& ohi, const GConst& g) {
    asm("{\n\t"
        ".reg .b64 t2,ax,d,r;\n\t"
        ".reg .f32 dl,dh;\n\t"
        "mov.b64 t2,{%2,%3};\n\t"
        "mul.rn.f32x2 ax,t2,%4;\n\t"
        "and.b64 ax,ax,%5;\n\t"
        "fma.rn.f32x2 d,ax,%6,%7;\n\t"
        "fma.rn.f32x2 d,d,ax,%8;\n\t"
        "fma.rn.f32x2 d,d,ax,%9;\n\t"
        "fma.rn.f32x2 d,d,ax,%10;\n\t"
        "fma.rn.f32x2 d,d,ax,%11;\n\t"
        "fma.rn.f32x2 d,d,ax,%12;\n\t"
        "mov.b64 {dl,dh},d;\n\t"
        "rcp.approx.f32 dl,dl;\n\t"
        "rcp.approx.f32 dh,dh;\n\t"
        "mov.b64 r,{dl,dh};\n\t"
        "mul.rn.f32x2 r,r,r;\n\t"
        "mul.rn.f32x2 r,r,r;\n\t"
        "mul.rn.f32x2 r,r,r;\n\t"
        "mul.rn.f32x2 r,r,r;\n\t"
        "fma.rn.f32x2 r,r,%13,%4;\n\t"
        "mul.rn.f32x2 d,ax,r;\n\t"
        "fma.rn.f32x2 d,t2,%14,d;\n\t"
        "mov.b64 {%0,%1},d;\n\t"
        "}"
        : "=f"(olo), "=f"(ohi)
        : "f"(tlo), "f"(thi),
          "l"(g.CINV), "l"(g.ABSM), "l"(g.A6), "l"(g.A5), "l"(g.A4),
          "l"(g.A3), "l"(g.A2), "l"(g.A1), "l"(g.ONE), "l"(g.NCV), "l"(g.HALF));
}

// ---------------- misc ----------------
__device__ __forceinline__ uint32_t f2tf(float f) {
    uint32_t r; asm("cvt.rna.tf32.f32 %0, %1;" : "=r"(r) : "f"(f)); return r;
}
__device__ __forceinline__ float f2tff(float f) { return __uint_as_float(f2tf(f)); }

__device__ __forceinline__ void mma_tf32(float c[4],
                                         uint32_t a0, uint32_t a1, uint32_t a2, uint32_t a3,
                                         uint32_t b0, uint32_t b1) {
    asm volatile("mma.sync.aligned.m16n8k8.row.col.f32.tf32.tf32.f32 "
                 "{%0,%1,%2,%3}, {%4,%5,%6,%7}, {%8,%9}, {%0,%1,%2,%3};"
                 : "+f"(c[0]), "+f"(c[1]), "+f"(c[2]), "+f"(c[3])
                 : "r"(a0), "r"(a1), "r"(a2), "r"(a3), "r"(b0), "r"(b1));
}

// warp GEMM m32: TWO m16 strips share ONE B-fragment stream (accumulating).
template <int NTILES>
__device__ __forceinline__ void warp_gemm2(const float* __restrict__ A,
                                           const float4* __restrict__ WF,
                                           float acc[2][NTILES][4],
                                           int m0, int n8base, int lr, int lc, int lane) {
    const float* ar0 = A + (m0 + lr) * 128;
    const float* ar1 = ar0 + 8 * 128;
    const float* ar2 = A + (m0 + 16 + lr) * 128;
    const float* ar3 = ar2 + 8 * 128;
    const float4* wb = WF + (size_t)(n8base * 8) * 32 + lane;
    const int sl = lr << 2;
    #pragma unroll
    for (int kp = 0; kp < 8; kp++) {
        float4 b[NTILES];
        #pragma unroll
        for (int nt = 0; nt < NTILES; nt++)
            b[nt] = __ldg(wb + (nt * 8 + kp) * 32);
        int i0 = (kp * 16 + lc) ^ sl;
        int i4 = i0 ^ 4;
        int j0 = (kp * 16 + 8 + lc) ^ sl;
        int j4 = j0 ^ 4;
        uint32_t a00 = __float_as_uint(ar0[i0]);
        uint32_t a01 = __float_as_uint(ar1[i0]);
        uint32_t a02 = __float_as_uint(ar0[i4]);
        uint32_t a03 = __float_as_uint(ar1[i4]);
        uint32_t a10 = __float_as_uint(ar2[i0]);
        uint32_t a11 = __float_as_uint(ar3[i0]);
        uint32_t a12 = __float_as_uint(ar2[i4]);
        uint32_t a13 = __float_as_uint(ar3[i4]);
        #pragma unroll
        for (int nt = 0; nt < NTILES; nt++) {
            mma_tf32(acc[0][nt], a00, a01, a02, a03,
                     __float_as_uint(b[nt].x), __float_as_uint(b[nt].y));
            mma_tf32(acc[1][nt], a10, a11, a12, a13,
                     __float_as_uint(b[nt].x), __float_as_uint(b[nt].y));
        }
        uint32_t c00 = __float_as_uint(ar0[j0]);
        uint32_t c01 = __float_as_uint(ar1[j0]);
        uint32_t c02 = __float_as_uint(ar0[j4]);
        uint32_t c03 = __float_as_uint(ar1[j4]);
        uint32_t c10 = __float_as_uint(ar2[j0]);
        uint32_t c11 = __float_as_uint(ar3[j0]);
        uint32_t c12 = __float_as_uint(ar2[j4]);
        uint32_t c13 = __float_as_uint(ar3[j4]);
        #pragma unroll
        for (int nt = 0; nt < NTILES; nt++) {
            mma_tf32(acc[0][nt], c00, c01, c02, c03,
                     __float_as_uint(b[nt].z), __float_as_uint(b[nt].w));
            mma_tf32(acc[1][nt], c10, c11, c12, c13,
                     __float_as_uint(b[nt].z), __float_as_uint(b[nt].w));
        }
    }
}

// ---------------- prep: fused weights + fragment images + fused bias ----------------
__device__ __forceinline__ int frag_idx(int k, int n) {
    return ((((n >> 3) * 8 + (k >> 4)) * 32 + (n & 7) * 4 + (k & 3)) << 2)
           + (((k >> 3) & 1) << 1) + ((k >> 2) & 1);
}
__global__ void prep_fused(const float* __restrict__ wn2, const float* __restrict__ we2,
                           const float* __restrict__ wc1, const float* __restrict__ wc2,
                           const float* __restrict__ node_b2, const float* __restrict__ edge_b2,
                           const float* __restrict__ comb_b1) {
    int stride = gridDim.x * blockDim.x;
    int t0 = blockIdx.x * blockDim.x + threadIdx.x;
    // fused weights: W~n[h][n] = sum_j Wn2[h][j]*Wc1[j][n]; W~e via Wc1[64+j][n]
    for (int i = t0; i < 128 * 128; i += stride) {
        int h = i >> 7, n = i & 127;
        float sn = 0.f, se = 0.f;
        #pragma unroll 4
        for (int j = 0; j < 64; j++) {
            float c_t = wc1[j * 128 + n];
            float c_b = wc1[(64 + j) * 128 + n];
            sn = fmaf(wn2[h * 64 + j], c_t, sn);
            se = fmaf(we2[h * 64 + j], c_b, se);
        }
        int idx = frag_idx(h, n);
        W_IMG[0     + idx] = f2tff(sn);
        W_IMG[16384 + idx] = f2tff(se);
    }
    // Wc2 fragment image (N=64)
    for (int i = t0; i < 128 * 64; i += stride) {
        int k = i >> 6, n = i & 63;
        W_IMG[32768 + frag_idx(k, n)] = f2tff(wc2[i]);
    }
    // fused bias
    for (int n = t0; n < 128; n += stride) {
        float s = comb_b1[n];
        for (int j = 0; j < 64; j++) {
            s = fmaf(node_b2[j], wc1[j * 128 + n], s);
            s = fmaf(7.f * edge_b2[j], wc1[(64 + j) * 128 + n], s);
        }
        BT[n] = s;
    }
}

// ---------------- main fused kernel: 2 CTAs/SM, m32 warp tiles, 6 barriers ----------------
__global__ void __launch_bounds__(NT, 2)
lifting_mma_kernel(const float* __restrict__ u0,      const float* __restrict__ x,
                   const float* __restrict__ node_w1, const float* __restrict__ node_b1,
                   const float* __restrict__ edge_w1, const float* __restrict__ edge_b1,
                   const float* __restrict__ comb_b2,
                   float* __restrict__ out)
{
    extern __shared__ float sm[];
    const int tid  = threadIdx.x;
    const int w    = tid >> 5;
    const int lane = tid & 31;
    const int lr   = lane >> 2, lc = lane & 3;
    const int blk  = blockIdx.x;
    const int bb   = blk / (NXV / TP);
    const int i0   = (blk % (NXV / TP)) * TP;
    const float* row_u = u0 + (size_t)bb * NXV;
    const float* row_x = x  + (size_t)bb * NXV;

    // ---- halo (clamped) ----
    for (int t = tid; t < TP + 6; t += NT) {
        int gi = i0 - 3 + t;
        gi = gi < 0 ? 0 : (gi > NXV - 1 ? NXV - 1 : gi);
        sm[S_U + t] = row_u[gi];
        sm[S_X + t] = row_x[gi];
    }
    __syncthreads();

    const GConst gc = make_gc();

    const int hh = tid & 127;       // hidden unit
    const int ph = tid >> 7;        // phase 0..1
    const int m0 = (w & 3) * 32;    // warp m32 tile base
    const int nh = w >> 2;          // warp n-half
    const int n8b  = nh * 4;        // N=64 fragment base (comb2)
    const int n8b1 = nh * 8;        // N=128 fragment base (fused GEMMs)
    const int nb   = nh * 32;
    const int nb1  = nh * 64;

    const float4* WFn = (const float4*)(W_IMG);            // fused node 128x128
    const float4* WFe = (const float4*)(W_IMG + 16384);    // fused edge 128x128
    const float4* WFc2 = (const float4*)(W_IMG + 32768);   // comb2 128x64

    // ---- accumulators for fused comb1 pre-activation (live across both GEMMs) ----
    float acc1a[2][4][4], acc1b[2][4][4];
    #pragma unroll
    for (int s = 0; s < 2; s++)
        #pragma unroll
        for (int i = 0; i < 4; i++) {
            acc1a[s][i][0]=acc1a[s][i][1]=acc1a[s][i][2]=acc1a[s][i][3]=0.f;
            acc1b[s][i][0]=acc1b[s][i][1]=acc1b[s][i][2]=acc1b[s][i][3]=0.f;
        }

    // ---- Stage 1: edge layer-1 (7-offset tanh-gelu sum) -> A ----
    {
        const float e0 = edge_w1[hh];
        const float e1 = edge_w1[128 + hh];
        const float e2 = edge_w1[256 + hh];
        const float eb = edge_b1[hh];
        const float e01 = e0 + e1;
        #pragma unroll 2
        for (int i = 0; i < 32; i++) {
            const int p0 = 2 * ph + 4 * i;
            float zz[8];
            #pragma unroll
            for (int j = 0; j < 8; j += 2) {
                float2 uu = *(const float2*)(sm + S_U + p0 + j);
                float2 xx = *(const float2*)(sm + S_X + p0 + j);
                zz[j]     = fmaf(e1, uu.x, e2 * xx.x);
                zz[j + 1] = fmaf(e1, uu.y, e2 * xx.y);
            }
            float ba = fmaf(e01, sm[S_U + p0 + 3], eb) - zz[3];
            float bc = fmaf(e01, sm[S_U + p0 + 4], eb) - zz[4];
            float sAl = 0.f, sAh = 0.f, sBl = 0.f, sBh = 0.f;
            #pragma unroll
            for (int o = 0; o < 7; o++) {
                float tlo = ba + zz[o];
                float thi = bc + zz[o + 1];
                if (o & 1) gelu_tanh_acc2(tlo, thi, sBl, sBh);
                else       gelu_tanh_acc2(tlo, thi, sAl, sAh);
            }
            sm[S_A + SW(p0, hh)]     = f2tff(sAl + sBl);
            sm[S_A + SW(p0 + 1, hh)] = f2tff(sAh + sBh);
        }
    }
    __syncthreads();

    // ---- fused edge GEMM: acc1 += G_e @ W~e (N=128) ----
    warp_gemm2<4>(sm + S_A, WFe, acc1a, m0, n8b1,     lr, lc, lane);
    warp_gemm2<4>(sm + S_A, WFe, acc1b, m0, n8b1 + 4, lr, lc, lane);
    __syncthreads();

    // ---- Stage 2: node layer-1 + tanh-gelu -> A ----
    {
        const float a0 = node_w1[hh];
        const float a1 = node_w1[128 + hh];
        const float nbb = node_b1[hh];
        #pragma unroll 2
        for (int i = 0; i < 32; i++) {
            const int p0 = 2 * ph + 4 * i;
            float va = fmaf(a0, sm[S_U + p0 + 3], fmaf(a1, sm[S_X + p0 + 3], nbb));
            float vb = fmaf(a0, sm[S_U + p0 + 4], fmaf(a1, sm[S_X + p0 + 4], nbb));
            float glo, ghi;
            gelu_tanh2p(va, vb, glo, ghi);
            sm[S_A + SW(p0, hh)]     = f2tff(glo);
            sm[S_A + SW(p0 + 1, hh)] = f2tff(ghi);
        }
    }
    __syncthreads();

    // ---- fused node GEMM: acc1 += G_n @ W~n (N=128) ----
    warp_gemm2<4>(sm + S_A, WFn, acc1a, m0, n8b1,     lr, lc, lane);
    warp_gemm2<4>(sm + S_A, WFn, acc1b, m0, n8b1 + 4, lr, lc, lane);
    __syncthreads();

    // ---- Stage 4: G2 = erf-gelu(acc1 + BT) -> A ----
    {
        const int sl = lr << 2;
        #pragma unroll
        for (int st = 0; st < 2; st++) {
            float* g0 = sm + S_A + (m0 + st * 16 + lr) * 128;
            float* g1 = g0 + 8 * 128;
            #pragma unroll
            for (int nt = 0; nt < 8; nt++) {
                const float (*ac)[4] = (nt < 4) ? acc1a[st] : acc1b[st];
                int ntl = nt & 3;
                int col = nb1 + nt * 8 + lc * 2;
                int sw  = col ^ sl;
                float2 bf = *(const float2*)(BT + col);
                float r0, r1, r2, r3;
                gelu2p(ac[ntl][0] + bf.x, ac[ntl][1] + bf.y, r0, r1, gc);
                gelu2p(ac[ntl][2] + bf.x, ac[ntl][3] + bf.y, r2, r3, gc);
                *(float2*)(g0 + sw) = make_float2(f2tff(r0), f2tff(r1));
                *(float2*)(g1 + sw) = make_float2(f2tff(r2), f2tff(r3));
            }
        }
    }
    __syncthreads();

    // ---- MMA comb2 + epilogue ----
    float acc2[2][4][4];
    #pragma unroll
    for (int s = 0; s < 2; s++)
        #pragma unroll
        for (int i = 0; i < 4; i++) { acc2[s][i][0]=acc2[s][i][1]=acc2[s][i][2]=acc2[s][i][3]=0.f; }
    warp_gemm2<4>(sm + S_A, WFc2, acc2, m0, n8b, lr, lc, lane);

    {
        #pragma unroll
        for (int st = 0; st < 2; st++) {
            float* orow0 = out + ((size_t)bb * NXV + i0 + m0 + st * 16 + lr) * 64;
            float* orow1 = orow0 + 8 * 64;
            #pragma unroll
            for (int nt = 0; nt < 4; nt++) {
                int colx = nb + nt * 8 + lc * 2;
                float2 b = *(const float2*)(comb_b2 + colx);
                *(float2*)(orow0 + colx) = make_float2(acc2[st][nt][0] + b.x, acc2[st][nt][1] + b.y);
                *(float2*)(orow1 + colx) = make_float2(acc2[st][nt][2] + b.x, acc2[st][nt][3] + b.y);
            }
        }
    }
}

extern "C" void kernel_launch(void* const* d_in, const int* in_sizes, int n_in,
                              void* d_out, int out_size)
{
    const float* u0      = (const float*)d_in[0];
    const float* x       = (const float*)d_in[1];
    const float* node_w1 = (const float*)d_in[2];
    const float* node_b1 = (const float*)d_in[3];
    const float* node_w2 = (const float*)d_in[4];
    const float* node_b2 = (const float*)d_in[5];
    const float* edge_w1 = (const float*)d_in[6];
    const float* edge_b1 = (const float*)d_in[7];
    const float* edge_w2 = (const float*)d_in[8];
    const float* edge_b2 = (const float*)d_in[9];
    const float* comb_w1 = (const float*)d_in[10];
    const float* comb_b1 = (const float*)d_in[11];
    const float* comb_w2 = (const float*)d_in[12];
    const float* comb_b2 = (const float*)d_in[13];
    float* out = (float*)d_out;

    prep_fused<<<128, 256>>>(node_w2, edge_w2, comb_w1, comb_w2,
                             node_b2, edge_b2, comb_b1);

    const size_t smem = SMEM_FLOATS * sizeof(float);
    cudaFuncSetAttribute(lifting_mma_kernel,
                         cudaFuncAttributeMaxDynamicSharedMemorySize, (int)smem);
    lifting_mma_kernel<<<NBLK, NT, smem>>>(u0, x,
                                           node_w1, node_b1,
                                           edge_w1, edge_b1,
                                           comb_b2,
                                           out);
}

// round 17
// speedup vs baseline: 1.7424x; 1.0295x over previous
#include <cuda_runtime.h>
#include <cstdint>
#include <math.h>

// ---------------- problem constants ----------------
#define NXV 16384
#define BV  16
#define TP  64            // points per block
#define NT  256           // threads per block (8 warps)
#define NBLK (BV * (NXV / TP))   // 4096

// ---------------- swizzled A-tile addressing ----------------
__device__ __forceinline__ int SW(int row, int k) {
    return row * 128 + (k ^ ((row & 7) << 2));
}

// ---------------- smem layout (float offsets) ----------------
#define S_A   0                  // activation / G2 buffer 64 x 128 (32KB)
#define S_U   8192               // u halo (70 -> 72)
#define S_X   (S_U + 72)
#define SMEM_FLOATS (S_X + 72)   // 33344 B -> 3 CTAs/SM

// weight images in GLOBAL: [0]=W~n (fused node,128x128), [16384]=W~e (fused edge),
// [32768]=Wc2 (128x64). W~n = Wn2 @ Wc1_top, W~e = We2 @ Wc1_bot.
#define WIMG_FLOATS 40960
__device__ __align__(16) float W_IMG[WIMG_FLOATS];
__device__ float BT[128];        // fused bias

typedef unsigned long long u64;

__device__ __forceinline__ u64 pk2(float lo, float hi) {
    u64 r; asm("mov.b64 %0,{%1,%2};" : "=l"(r) : "f"(lo), "f"(hi)); return r;
}

// ---------------- tanh-gelu (stages 1 & 2) ----------------
#define P_GC1  0x3F4C422A3F4C422AULL   // 0.79788456 x2
#define P_GC2  0x3D12220F3D12220FULL   // 0.03567741 x2
#define P_HALFP 0x3F0000003F000000ULL  // 0.5 x2
__device__ __forceinline__ void gelu_tanh_acc2(float tlo, float thi,
                                               float& slo, float& shi) {
    asm("{\n\t"
        ".reg .b64 t2,s2,sq,q,a,h;\n\t"
        ".reg .f32 al,ah;\n\t"
        "mov.b64 t2,{%2,%3};\n\t"
        "mov.b64 s2,{%0,%1};\n\t"
        "mul.rn.f32x2 sq,t2,t2;\n\t"
        "fma.rn.f32x2 q,sq,%5,%4;\n\t"
        "mul.rn.f32x2 a,t2,q;\n\t"
        "mov.b64 {al,ah},a;\n\t"
        "tanh.approx.f32 al,al;\n\t"
        "tanh.approx.f32 ah,ah;\n\t"
        "mov.b64 h,{al,ah};\n\t"
        "fma.rn.f32x2 h,h,%6,%6;\n\t"
        "fma.rn.f32x2 s2,t2,h,s2;\n\t"
        "mov.b64 {%0,%1},s2;\n\t"
        "}"
        : "+f"(slo), "+f"(shi)
        : "f"(tlo), "f"(thi),
          "l"((u64)P_GC1), "l"((u64)P_GC2), "l"((u64)P_HALFP));
}
__device__ __forceinline__ void gelu_tanh2p(float tlo, float thi,
                                            float& olo, float& ohi) {
    asm("{\n\t"
        ".reg .b64 t2,sq,q,a,h;\n\t"
        ".reg .f32 al,ah;\n\t"
        "mov.b64 t2,{%2,%3};\n\t"
        "mul.rn.f32x2 sq,t2,t2;\n\t"
        "fma.rn.f32x2 q,sq,%5,%4;\n\t"
        "mul.rn.f32x2 a,t2,q;\n\t"
        "mov.b64 {al,ah},a;\n\t"
        "tanh.approx.f32 al,al;\n\t"
        "tanh.approx.f32 ah,ah;\n\t"
        "mov.b64 h,{al,ah};\n\t"
        "fma.rn.f32x2 h,h,%6,%6;\n\t"
        "mul.rn.f32x2 h,t2,h;\n\t"
        "mov.b64 {%0,%1},h;\n\t"
        "}"
        : "=f"(olo), "=f"(ohi)
        : "f"(tlo), "f"(thi),
          "l"((u64)P_GC1), "l"((u64)P_GC2), "l"((u64)P_HALFP));
}

// ---------------- A&S 7.1.28 erf-gelu (stage 4) ----------------
struct GConst { u64 CINV, ABSM, A6, A5, A4, A3, A2, A1, ONE, NCV, HALF; };
__device__ __forceinline__ GConst make_gc() {
    GConst g;
    g.CINV = 0x3F3504F33F3504F3ULL;
    g.ABSM = 0x7FFFFFFF7FFFFFFFULL;
    g.A6   = pk2(0.0000430638f, 0.0000430638f);
    g.A5   = pk2(0.0002765672f, 0.0002765672f);
    g.A4   = pk2(0.0001520143f, 0.0001520143f);
    g.A3   = pk2(0.0092705272f, 0.0092705272f);
    g.A2   = pk2(0.0422820123f, 0.0422820123f);
    g.A1   = pk2(0.0705230784f, 0.0705230784f);
    g.ONE  = 0x3F8000003F800000ULL;
    g.NCV  = 0xBF3504F3BF3504F3ULL;
    g.HALF = 0x3F0000003F000000ULL;
    return g;
}
__device__ __forceinline__ void gelu2p(float tlo, float thi,
                                       float& olo, float& ohi, const GConst& g) {
    asm("{\n\t"
        ".reg .b64 t2,ax,d,r;\n\t"
        ".reg .f32 dl,dh;\n\t"
        "mov.b64 t2,{%2,%3};\n\t"
        "mul.rn.f32x2 ax,t2,%4;\n\t"
        "and.b64 ax,ax,%5;\n\t"
        "fma.rn.f32x2 d,ax,%6,%7;\n\t"
        "fma.rn.f32x2 d,d,ax,%8;\n\t"
        "fma.rn.f32x2 d,d,ax,%9;\n\t"
        "fma.rn.f32x2 d,d,ax,%10;\n\t"
        "fma.rn.f32x2 d,d,ax,%11;\n\t"
        "fma.rn.f32x2 d,d,ax,%12;\n\t"
        "mov.b64 {dl,dh},d;\n\t"
        "rcp.approx.f32 dl,dl;\n\t"
        "rcp.approx.f32 dh,dh;\n\t"
        "mov.b64 r,{dl,dh};\n\t"
        "mul.rn.f32x2 r,r,r;\n\t"
        "mul.rn.f32x2 r,r,r;\n\t"
        "mul.rn.f32x2 r,r,r;\n\t"
        "mul.rn.f32x2 r,r,r;\n\t"
        "fma.rn.f32x2 r,r,%13,%4;\n\t"
        "mul.rn.f32x2 d,ax,r;\n\t"
        "fma.rn.f32x2 d,t2,%14,d;\n\t"
        "mov.b64 {%0,%1},d;\n\t"
        "}"
        : "=f"(olo), "=f"(ohi)
        : "f"(tlo), "f"(thi),
          "l"(g.CINV), "l"(g.ABSM), "l"(g.A6), "l"(g.A5), "l"(g.A4),
          "l"(g.A3), "l"(g.A2), "l"(g.A1), "l"(g.ONE), "l"(g.NCV), "l"(g.HALF));
}

// ---------------- misc ----------------
__device__ __forceinline__ uint32_t f2tf(float f) {
    uint32_t r; asm("cvt.rna.tf32.f32 %0, %1;" : "=r"(r) : "f"(f)); return r;
}
__device__ __forceinline__ float f2tff(float f) { return __uint_as_float(f2tf(f)); }

__device__ __forceinline__ void mma_tf32(float c[4],
                                         uint32_t a0, uint32_t a1, uint32_t a2, uint32_t a3,
                                         uint32_t b0, uint32_t b1) {
    asm volatile("mma.sync.aligned.m16n8k8.row.col.f32.tf32.tf32.f32 "
                 "{%0,%1,%2,%3}, {%4,%5,%6,%7}, {%8,%9}, {%0,%1,%2,%3};"
                 : "+f"(c[0]), "+f"(c[1]), "+f"(c[2]), "+f"(c[3])
                 : "r"(a0), "r"(a1), "r"(a2), "r"(a3), "r"(b0), "r"(b1));
}

// warp GEMM m32: TWO m16 strips share ONE B-fragment stream (accumulating).
// B image layout: [n8][kp(8)][lane] float4 {b0(2kp),b1(2kp),b0(2kp+1),b1(2kp+1)}
template <int NTILES>
__device__ __forceinline__ void warp_gemm2(const float* __restrict__ A,
                                           const float4* __restrict__ WF,
                                           float acc[2][NTILES][4],
                                           int m0, int n8base, int lr, int lc, int lane) {
    const float* ar0 = A + (m0 + lr) * 128;
    const float* ar1 = ar0 + 8 * 128;
    const float* ar2 = A + (m0 + 16 + lr) * 128;
    const float* ar3 = ar2 + 8 * 128;
    const float4* wb = WF + (size_t)(n8base * 8) * 32 + lane;
    const int sl = lr << 2;
    #pragma unroll
    for (int kp = 0; kp < 8; kp++) {
        float4 b[NTILES];
        #pragma unroll
        for (int nt = 0; nt < NTILES; nt++)
            b[nt] = __ldg(wb + (nt * 8 + kp) * 32);
        int i0 = (kp * 16 + lc) ^ sl;
        int i4 = i0 ^ 4;
        int j0 = (kp * 16 + 8 + lc) ^ sl;
        int j4 = j0 ^ 4;
        uint32_t a00 = __float_as_uint(ar0[i0]);
        uint32_t a01 = __float_as_uint(ar1[i0]);
        uint32_t a02 = __float_as_uint(ar0[i4]);
        uint32_t a03 = __float_as_uint(ar1[i4]);
        uint32_t a10 = __float_as_uint(ar2[i0]);
        uint32_t a11 = __float_as_uint(ar3[i0]);
        uint32_t a12 = __float_as_uint(ar2[i4]);
        uint32_t a13 = __float_as_uint(ar3[i4]);
        #pragma unroll
        for (int nt = 0; nt < NTILES; nt++) {
            mma_tf32(acc[0][nt], a00, a01, a02, a03,
                     __float_as_uint(b[nt].x), __float_as_uint(b[nt].y));
            mma_tf32(acc[1][nt], a10, a11, a12, a13,
                     __float_as_uint(b[nt].x), __float_as_uint(b[nt].y));
        }
        uint32_t c00 = __float_as_uint(ar0[j0]);
        uint32_t c01 = __float_as_uint(ar1[j0]);
        uint32_t c02 = __float_as_uint(ar0[j4]);
        uint32_t c03 = __float_as_uint(ar1[j4]);
        uint32_t c10 = __float_as_uint(ar2[j0]);
        uint32_t c11 = __float_as_uint(ar3[j0]);
        uint32_t c12 = __float_as_uint(ar2[j4]);
        uint32_t c13 = __float_as_uint(ar3[j4]);
        #pragma unroll
        for (int nt = 0; nt < NTILES; nt++) {
            mma_tf32(acc[0][nt], c00, c01, c02, c03,
                     __float_as_uint(b[nt].z), __float_as_uint(b[nt].w));
            mma_tf32(acc[1][nt], c10, c11, c12, c13,
                     __float_as_uint(b[nt].z), __float_as_uint(b[nt].w));
        }
    }
}

// ---------------- prep: fused weights + fragment images + fused bias ----------------
__device__ __forceinline__ int frag_idx(int k, int n) {
    return ((((n >> 3) * 8 + (k >> 4)) * 32 + (n & 7) * 4 + (k & 3)) << 2)
           + (((k >> 3) & 1) << 1) + ((k >> 2) & 1);
}
__global__ void prep_fused(const float* __restrict__ wn2, const float* __restrict__ we2,
                           const float* __restrict__ wc1, const float* __restrict__ wc2,
                           const float* __restrict__ node_b2, const float* __restrict__ edge_b2,
                           const float* __restrict__ comb_b1) {
    int stride = gridDim.x * blockDim.x;
    int t0 = blockIdx.x * blockDim.x + threadIdx.x;
    for (int i = t0; i < 128 * 128; i += stride) {
        int h = i >> 7, n = i & 127;
        float sn = 0.f, se = 0.f;
        #pragma unroll 4
        for (int j = 0; j < 64; j++) {
            float c_t = wc1[j * 128 + n];
            float c_b = wc1[(64 + j) * 128 + n];
            sn = fmaf(wn2[h * 64 + j], c_t, sn);
            se = fmaf(we2[h * 64 + j], c_b, se);
        }
        int idx = frag_idx(h, n);
        W_IMG[0     + idx] = f2tff(sn);
        W_IMG[16384 + idx] = f2tff(se);
    }
    for (int i = t0; i < 128 * 64; i += stride) {
        int k = i >> 6, n = i & 63;
        W_IMG[32768 + frag_idx(k, n)] = f2tff(wc2[i]);
    }
    for (int n = t0; n < 128; n += stride) {
        float s = comb_b1[n];
        for (int j = 0; j < 64; j++) {
            s = fmaf(node_b2[j], wc1[j * 128 + n], s);
            s = fmaf(7.f * edge_b2[j], wc1[(64 + j) * 128 + n], s);
        }
        BT[n] = s;
    }
}

// ---------------- main fused kernel: 3 CTAs/SM, m32 x n-quarter warp tiles ----------------
__global__ void __launch_bounds__(NT, 3)
lifting_mma_kernel(const float* __restrict__ u0,      const float* __restrict__ x,
                   const float* __restrict__ node_w1, const float* __restrict__ node_b1,
                   const float* __restrict__ edge_w1, const float* __restrict__ edge_b1,
                   const float* __restrict__ comb_b2,
                   float* __restrict__ out)
{
    extern __shared__ float sm[];
    const int tid  = threadIdx.x;
    const int w    = tid >> 5;
    const int lane = tid & 31;
    const int lr   = lane >> 2, lc = lane & 3;
    const int blk  = blockIdx.x;
    const int bb   = blk / (NXV / TP);
    const int i0   = (blk % (NXV / TP)) * TP;
    const float* row_u = u0 + (size_t)bb * NXV;
    const float* row_x = x  + (size_t)bb * NXV;

    // ---- halo (clamped) ----
    for (int t = tid; t < TP + 6; t += NT) {
        int gi = i0 - 3 + t;
        gi = gi < 0 ? 0 : (gi > NXV - 1 ? NXV - 1 : gi);
        sm[S_U + t] = row_u[gi];
        sm[S_X + t] = row_x[gi];
    }
    __syncthreads();

    const GConst gc = make_gc();

    const int hh = tid & 127;       // hidden unit
    const int ph = tid >> 7;        // phase 0..1
    const int m0 = (w & 1) * 32;    // warp m32 tile base (2 tiles)
    const int nq = w >> 1;          // n-quarter (0..3)
    const int n8b1 = nq * 4;        // fused N=128 GEMM fragment base (32 cols)
    const int nb1  = nq * 32;
    const int n8b  = nq * 2;        // comb2 N=64 fragment base (16 cols)
    const int nbc  = nq * 16;

    const float4* WFn  = (const float4*)(W_IMG);           // fused node 128x128
    const float4* WFe  = (const float4*)(W_IMG + 16384);   // fused edge 128x128
    const float4* WFc2 = (const float4*)(W_IMG + 32768);   // comb2 128x64

    // ---- Stage 1: edge layer-1 (7-offset tanh-gelu sum) -> A ----
    {
        const float e0 = edge_w1[hh];
        const float e1 = edge_w1[128 + hh];
        const float e2 = edge_w1[256 + hh];
        const float eb = edge_b1[hh];
        const float e01 = e0 + e1;
        #pragma unroll 2
        for (int i = 0; i < 16; i++) {
            const int p0 = 2 * ph + 4 * i;      // pair (p0, p0+1) covers 0..63
            float zz[8];
            #pragma unroll
            for (int j = 0; j < 8; j += 2) {
                float2 uu = *(const float2*)(sm + S_U + p0 + j);
                float2 xx = *(const float2*)(sm + S_X + p0 + j);
                zz[j]     = fmaf(e1, uu.x, e2 * xx.x);
                zz[j + 1] = fmaf(e1, uu.y, e2 * xx.y);
            }
            float ba = fmaf(e01, sm[S_U + p0 + 3], eb) - zz[3];
            float bc = fmaf(e01, sm[S_U + p0 + 4], eb) - zz[4];
            float sAl = 0.f, sAh = 0.f, sBl = 0.f, sBh = 0.f;
            #pragma unroll
            for (int o = 0; o < 7; o++) {
                float tlo = ba + zz[o];
                float thi = bc + zz[o + 1];
                if (o & 1) gelu_tanh_acc2(tlo, thi, sBl, sBh);
                else       gelu_tanh_acc2(tlo, thi, sAl, sAh);
            }
            sm[S_A + SW(p0, hh)]     = f2tff(sAl + sBl);
            sm[S_A + SW(p0 + 1, hh)] = f2tff(sAh + sBh);
        }
    }
    __syncthreads();

    // ---- accumulators for fused comb1 pre-activation ----
    float acc1[2][4][4];
    #pragma unroll
    for (int s = 0; s < 2; s++)
        #pragma unroll
        for (int i = 0; i < 4; i++) { acc1[s][i][0]=acc1[s][i][1]=acc1[s][i][2]=acc1[s][i][3]=0.f; }

    // ---- fused edge GEMM: acc1 += G_e @ W~e (N=128, warp quarter) ----
    warp_gemm2<4>(sm + S_A, WFe, acc1, m0, n8b1, lr, lc, lane);
    __syncthreads();

    // ---- Stage 2: node layer-1 + tanh-gelu -> A ----
    {
        const float a0 = node_w1[hh];
        const float a1 = node_w1[128 + hh];
        const float nbb = node_b1[hh];
        #pragma unroll 2
        for (int i = 0; i < 16; i++) {
            const int p0 = 2 * ph + 4 * i;
            float va = fmaf(a0, sm[S_U + p0 + 3], fmaf(a1, sm[S_X + p0 + 3], nbb));
            float vb = fmaf(a0, sm[S_U + p0 + 4], fmaf(a1, sm[S_X + p0 + 4], nbb));
            float glo, ghi;
            gelu_tanh2p(va, vb, glo, ghi);
            sm[S_A + SW(p0, hh)]     = f2tff(glo);
            sm[S_A + SW(p0 + 1, hh)] = f2tff(ghi);
        }
    }
    __syncthreads();

    // ---- fused node GEMM: acc1 += G_n @ W~n ----
    warp_gemm2<4>(sm + S_A, WFn, acc1, m0, n8b1, lr, lc, lane);
    __syncthreads();

    // ---- Stage 4: G2 = erf-gelu(acc1 + BT) -> A ----
    {
        const int sl = lr << 2;
        #pragma unroll
        for (int st = 0; st < 2; st++) {
            float* g0 = sm + S_A + (m0 + st * 16 + lr) * 128;
            float* g1 = g0 + 8 * 128;
            #pragma unroll
            for (int nt = 0; nt < 4; nt++) {
                int col = nb1 + nt * 8 + lc * 2;
                int sw  = col ^ sl;
                float2 bf = *(const float2*)(BT + col);
                float r0, r1, r2, r3;
                gelu2p(acc1[st][nt][0] + bf.x, acc1[st][nt][1] + bf.y, r0, r1, gc);
                gelu2p(acc1[st][nt][2] + bf.x, acc1[st][nt][3] + bf.y, r2, r3, gc);
                *(float2*)(g0 + sw) = make_float2(f2tff(r0), f2tff(r1));
                *(float2*)(g1 + sw) = make_float2(f2tff(r2), f2tff(r3));
            }
        }
    }
    __syncthreads();

    // ---- MMA comb2 + epilogue ----
    float acc2[2][2][4];
    #pragma unroll
    for (int s = 0; s < 2; s++)
        #pragma unroll
        for (int i = 0; i < 2; i++) { acc2[s][i][0]=acc2[s][i][1]=acc2[s][i][2]=acc2[s][i][3]=0.f; }
    warp_gemm2<2>(sm + S_A, WFc2, acc2, m0, n8b, lr, lc, lane);

    {
        #pragma unroll
        for (int st = 0; st < 2; st++) {
            float* orow0 = out + ((size_t)bb * NXV + i0 + m0 + st * 16 + lr) * 64;
            float* orow1 = orow0 + 8 * 64;
            #pragma unroll
            for (int nt = 0; nt < 2; nt++) {
                int colx = nbc + nt * 8 + lc * 2;
                float2 b = *(const float2*)(comb_b2 + colx);
                *(float2*)(orow0 + colx) = make_float2(acc2[st][nt][0] + b.x, acc2[st][nt][1] + b.y);
                *(float2*)(orow1 + colx) = make_float2(acc2[st][nt][2] + b.x, acc2[st][nt][3] + b.y);
            }
        }
    }
}

extern "C" void kernel_launch(void* const* d_in, const int* in_sizes, int n_in,
                              void* d_out, int out_size)
{
    const float* u0      = (const float*)d_in[0];
    const float* x       = (const float*)d_in[1];
    const float* node_w1 = (const float*)d_in[2];
    const float* node_b1 = (const float*)d_in[3];
    const float* node_w2 = (const float*)d_in[4];
    const float* node_b2 = (const float*)d_in[5];
    const float* edge_w1 = (const float*)d_in[6];
    const float* edge_b1 = (const float*)d_in[7];
    const float* edge_w2 = (const float*)d_in[8];
    const float* edge_b2 = (const float*)d_in[9];
    const float* comb_w1 = (const float*)d_in[10];
    const float* comb_b1 = (const float*)d_in[11];
    const float* comb_w2 = (const float*)d_in[12];
    const float* comb_b2 = (const float*)d_in[13];
    float* out = (float*)d_out;

    prep_fused<<<128, 256>>>(node_w2, edge_w2, comb_w1, comb_w2,
                             node_b2, edge_b2, comb_b1);

    const size_t smem = SMEM_FLOATS * sizeof(float);
    cudaFuncSetAttribute(lifting_mma_kernel,
                         cudaFuncAttributeMaxDynamicSharedMemorySize, (int)smem);
    lifting_mma_kernel<<<NBLK, NT, smem>>>(u0, x,
                                           node_w1, node_b1,
                                           edge_w1, edge_b1,
                                           comb_b2,
                                           out);
}